// round 1
// baseline (speedup 1.0000x reference)
#include <cuda_runtime.h>
#include <cstdint>

#define Q  4
#define K  4096
#define D  256
#define NTOK_MAX 32768
#define NX_MAX   (NTOK_MAX * D)

// Scratch (device globals: allocation-free rule)
__device__ float               g_res[NX_MAX];       // residual [N, D]
__device__ float               g_c2[Q * K];         // ||c||^2 per code per layer
__device__ unsigned long long  g_best[NTOK_MAX];    // packed (scorekey<<32)|codeidx
__device__ float               g_loss[Q];

// ---------------------------------------------------------------------------
// residual = x
__global__ void copy_res_kernel(const float* __restrict__ x, int nx4) {
    int i = blockIdx.x * blockDim.x + threadIdx.x;
    if (i < nx4) {
        reinterpret_cast<float4*>(g_res)[i] = reinterpret_cast<const float4*>(x)[i];
    }
}

// ---------------------------------------------------------------------------
// g_c2[row] = sum(cb[row]^2); also zero the loss accumulators
__global__ void c2_kernel(const float* __restrict__ cb) {
    if (blockIdx.x == 0 && threadIdx.x < Q) g_loss[threadIdx.x] = 0.f;
    int row  = blockIdx.x * 8 + (threadIdx.x >> 5);
    int lane = threadIdx.x & 31;
    const float* p = cb + (size_t)row * D;
    float s = 0.f;
#pragma unroll
    for (int t = 0; t < 2; t++) {
        float4 v = *reinterpret_cast<const float4*>(p + lane * 4 + t * 128);
        s += v.x * v.x + v.y * v.y + v.z * v.z + v.w * v.w;
    }
#pragma unroll
    for (int o = 16; o; o >>= 1) s += __shfl_down_sync(0xFFFFFFFFu, s, o);
    if (!lane) g_c2[row] = s;
}

// ---------------------------------------------------------------------------
__global__ void init_best_kernel(int n_tok) {
    int i = blockIdx.x * blockDim.x + threadIdx.x;
    if (i < n_tok) g_best[i] = 0xFFFFFFFFFFFFFFFFull;
}

// ---------------------------------------------------------------------------
// Distance GEMM + fused argmin. 128 tokens x 128 codes per block, BK=16.
// Packed fp32x2 accumulators: acc[i][j2] holds codes {2tx+32j2, 2tx+32j2+1}.
__global__ __launch_bounds__(256, 2)
void dist_kernel(const float* __restrict__ cb, int layer) {
    __shared__ float As[16][128];
    __shared__ float Bs[16][128];
    __shared__ unsigned long long red[128][17];   // padded: conflict-free reduce

    const int tid = threadIdx.x;
    const int tx  = tid & 15;
    const int ty  = tid >> 4;
    const int rowA = blockIdx.x * 128;            // token base
    const int rowB = blockIdx.y * 128;            // code base
    const float* __restrict__ cbL = cb + (size_t)layer * K * D;

    unsigned long long acc[8][4];
#pragma unroll
    for (int i = 0; i < 8; i++)
#pragma unroll
        for (int j = 0; j < 4; j++) acc[i][j] = 0ull;

    for (int dk = 0; dk < D; dk += 16) {
#pragma unroll
        for (int p = 0; p < 2; p++) {
            int f4 = tid + p * 256;               // 0..511
            int r  = f4 >> 2;
            int c  = (f4 & 3) << 2;
            float4 va = *reinterpret_cast<const float4*>(
                g_res + (size_t)(rowA + r) * D + dk + c);
            As[c + 0][r] = va.x; As[c + 1][r] = va.y;
            As[c + 2][r] = va.z; As[c + 3][r] = va.w;
            float4 vb = *reinterpret_cast<const float4*>(
                cbL + (size_t)(rowB + r) * D + dk + c);
            Bs[c + 0][r] = vb.x; Bs[c + 1][r] = vb.y;
            Bs[c + 2][r] = vb.z; Bs[c + 3][r] = vb.w;
        }
        __syncthreads();
#pragma unroll
        for (int d = 0; d < 16; d++) {
            // B fragment: u64 index tx + 16*j  -> floats {2tx+32j, 2tx+32j+1}
            const unsigned long long* bp =
                reinterpret_cast<const unsigned long long*>(&Bs[d][0]);
            unsigned long long b2[4];
#pragma unroll
            for (int j = 0; j < 4; j++) b2[j] = bp[tx + 16 * j];

            float4 a0 = *reinterpret_cast<const float4*>(&As[d][ty * 8]);
            float4 a1 = *reinterpret_cast<const float4*>(&As[d][ty * 8 + 4]);
            float av[8] = {a0.x, a0.y, a0.z, a0.w, a1.x, a1.y, a1.z, a1.w};
#pragma unroll
            for (int i = 0; i < 8; i++) {
                float2 tdup = make_float2(av[i], av[i]);
                unsigned long long a2 =
                    *reinterpret_cast<unsigned long long*>(&tdup);
#pragma unroll
                for (int j = 0; j < 4; j++)
                    asm("fma.rn.f32x2 %0, %1, %2, %0;"
                        : "+l"(acc[i][j]) : "l"(a2), "l"(b2[j]));
            }
        }
        __syncthreads();
    }

    // Epilogue: score = ||c||^2 - 2*dot ; argmin with lowest-index tie-break
    float c2v[8];
#pragma unroll
    for (int j = 0; j < 4; j++) {
        int code = rowB + 2 * tx + 32 * j;
        c2v[2 * j]     = g_c2[layer * K + code];
        c2v[2 * j + 1] = g_c2[layer * K + code + 1];
    }
#pragma unroll
    for (int i = 0; i < 8; i++) {
        float    bs = __int_as_float(0x7f800000);
        unsigned bi = 0;
#pragma unroll
        for (int j = 0; j < 4; j++) {
            float2 dv = *reinterpret_cast<float2*>(&acc[i][j]);
            int code  = rowB + 2 * tx + 32 * j;
            float s0  = fmaf(-2.f, dv.x, c2v[2 * j]);
            float s1  = fmaf(-2.f, dv.y, c2v[2 * j + 1]);
            if (s0 < bs) { bs = s0; bi = (unsigned)code; }
            if (s1 < bs) { bs = s1; bi = (unsigned)(code + 1); }
        }
        unsigned kb = __float_as_uint(bs);
        kb = (kb & 0x80000000u) ? ~kb : (kb | 0x80000000u);  // orderable fp32
        red[ty * 8 + i][tx] = ((unsigned long long)kb << 32) | bi;
    }
    __syncthreads();
    if (tid < 128) {
        unsigned long long m = red[tid][0];
#pragma unroll
        for (int t = 1; t < 16; t++) {
            unsigned long long v = red[tid][t];
            m = (v < m) ? v : m;
        }
        atomicMin(&g_best[rowA + tid], m);
    }
}

// ---------------------------------------------------------------------------
// Per token: idx -> write index output, residual -= codeword, commit loss.
__global__ void update_kernel(const float* __restrict__ cb,
                              float* __restrict__ out,
                              int layer, int n_tok, int idx_base) {
    int token = blockIdx.x * 8 + (threadIdx.x >> 5);
    int lane  = threadIdx.x & 31;
    if (token >= n_tok) return;
    unsigned long long key = g_best[token];
    int idx = (int)(unsigned)(key & 0xFFFFFFFFull);
    const float* q = cb + ((size_t)layer * K + idx) * D;
    float* r = g_res + (size_t)token * D;
    float local = 0.f;
#pragma unroll
    for (int t = 0; t < 2; t++) {
        int d = lane * 4 + t * 128;
        float4 rv = *reinterpret_cast<float4*>(r + d);
        float4 qv = *reinterpret_cast<const float4*>(q + d);
        rv.x -= qv.x; rv.y -= qv.y; rv.z -= qv.z; rv.w -= qv.w;
        local += rv.x * rv.x + rv.y * rv.y + rv.z * rv.z + rv.w * rv.w;
        *reinterpret_cast<float4*>(r + d) = rv;
    }
#pragma unroll
    for (int o = 16; o; o >>= 1) local += __shfl_down_sync(0xFFFFFFFFu, local, o);
    if (!lane) {
        out[idx_base + layer * n_tok + token] = (float)idx;
        atomicAdd(&g_loss[layer], local);
    }
}

// ---------------------------------------------------------------------------
// quantized_out = x - residual_final ; losses
__global__ void finalize_kernel(const float* __restrict__ x,
                                float* __restrict__ out,
                                int nx4, int loss_off, float invND) {
    int i = blockIdx.x * blockDim.x + threadIdx.x;
    if (i < nx4) {
        float4 xv = reinterpret_cast<const float4*>(x)[i];
        float4 rv = reinterpret_cast<const float4*>(g_res)[i];
        float4 o;
        o.x = xv.x - rv.x; o.y = xv.y - rv.y;
        o.z = xv.z - rv.z; o.w = xv.w - rv.w;
        reinterpret_cast<float4*>(out)[i] = o;
    }
    if (blockIdx.x == 0 && threadIdx.x < Q)
        out[loss_off + threadIdx.x] = g_loss[threadIdx.x] * invND;
}

// ---------------------------------------------------------------------------
extern "C" void kernel_launch(void* const* d_in, const int* in_sizes, int n_in,
                              void* d_out, int out_size) {
    const float* x  = (const float*)d_in[0];   // [8, 4096, 256] fp32
    const float* cb = (const float*)d_in[1];   // [4, 4096, 256] fp32
    float* out = (float*)d_out;

    int nx    = in_sizes[0];      // 8388608
    int n_tok = nx / D;           // 32768
    int nx4   = nx / 4;

    copy_res_kernel<<<(nx4 + 255) / 256, 256>>>(x, nx4);
    c2_kernel<<<(Q * K) / 8, 256>>>(cb);

    for (int qi = 0; qi < Q; qi++) {
        init_best_kernel<<<(n_tok + 255) / 256, 256>>>(n_tok);
        dist_kernel<<<dim3(n_tok / 128, K / 128), 256>>>(cb, qi);
        update_kernel<<<n_tok / 8, 256>>>(cb, out, qi, n_tok, nx);
    }

    finalize_kernel<<<(nx4 + 255) / 256, 256>>>(
        x, out, nx4, nx + Q * n_tok, 1.f / (float)nx);
}

// round 3
// speedup vs baseline: 3.6473x; 3.6473x over previous
#include <cuda_runtime.h>
#include <cuda_bf16.h>
#include <cstdint>

#define Q  4
#define K  4096
#define D  256
#define NTOK_MAX 32768
#define NX_MAX   (NTOK_MAX * D)
#define CB_ELEMS (Q * K * D)

// ---------------- device scratch (allocation-free rule) ----------------
__device__ float               g_res[NX_MAX];         // residual [N, D] fp32
__device__ __nv_bfloat16       g_rb[NX_MAX];          // residual bf16
__device__ __nv_bfloat16       g_cbb[CB_ELEMS];       // codebook bf16
__device__ float               g_c2[Q * K];           // exact ||c||^2
__device__ unsigned long long  g_cand[NTOK_MAX * 8];  // 8 coarse cands/token
__device__ unsigned long long  g_best[NTOK_MAX];      // exact (key<<32)|idx
__device__ float               g_loss[Q];

// ---------------- helpers ----------------
__device__ __forceinline__ uint32_t smem_u32(const void* p) {
    uint32_t a;
    asm("{ .reg .u64 t; cvta.to.shared.u64 t, %1; cvt.u32.u64 %0, t; }"
        : "=r"(a) : "l"(p));
    return a;
}
__device__ __forceinline__ unsigned long long pack_key(float s, int code) {
    unsigned u = __float_as_uint(s);
    u = (u & 0x80000000u) ? ~u : (u | 0x80000000u);   // orderable fp32
    return ((unsigned long long)u << 32) | (unsigned)code;
}
__device__ __forceinline__ void cp16(uint32_t dst, const void* src) {
    asm volatile("cp.async.cg.shared.global [%0], [%1], 16;"
                 :: "r"(dst), "l"(src));
}
__device__ __forceinline__ void ldsm_x4(uint32_t& r0, uint32_t& r1,
                                        uint32_t& r2, uint32_t& r3, uint32_t a) {
    asm volatile("ldmatrix.sync.aligned.m8n8.x4.shared.b16 {%0,%1,%2,%3}, [%4];"
                 : "=r"(r0), "=r"(r1), "=r"(r2), "=r"(r3) : "r"(a));
}
__device__ __forceinline__ void mma16816(float* d, const uint32_t* a,
                                         const uint32_t* b) {
    asm volatile(
        "mma.sync.aligned.m16n8k16.row.col.f32.bf16.bf16.f32 "
        "{%0,%1,%2,%3},{%4,%5,%6,%7},{%8,%9},{%0,%1,%2,%3};"
        : "+f"(d[0]), "+f"(d[1]), "+f"(d[2]), "+f"(d[3])
        : "r"(a[0]), "r"(a[1]), "r"(a[2]), "r"(a[3]), "r"(b[0]), "r"(b[1]));
}

// ---------------------------------------------------------------------------
__global__ void copy_res_kernel(const float* __restrict__ x, int nx4) {
    int i = blockIdx.x * blockDim.x + threadIdx.x;
    if (i < nx4)
        reinterpret_cast<float4*>(g_res)[i] = reinterpret_cast<const float4*>(x)[i];
}

// exact ||c||^2 and zero losses
__global__ void c2_kernel(const float* __restrict__ cb) {
    if (blockIdx.x == 0 && threadIdx.x < Q) g_loss[threadIdx.x] = 0.f;
    int row  = blockIdx.x * 8 + (threadIdx.x >> 5);
    int lane = threadIdx.x & 31;
    const float* p = cb + (size_t)row * D;
    float s = 0.f;
#pragma unroll
    for (int t = 0; t < 2; t++) {
        float4 v = *reinterpret_cast<const float4*>(p + lane * 4 + t * 128);
        s += v.x * v.x + v.y * v.y + v.z * v.z + v.w * v.w;
    }
#pragma unroll
    for (int o = 16; o; o >>= 1) s += __shfl_down_sync(0xFFFFFFFFu, s, o);
    if (!lane) g_c2[row] = s;
}

__device__ __forceinline__ ushort4 to_bf4(float4 v) {
    return ushort4{__bfloat16_as_ushort(__float2bfloat16_rn(v.x)),
                   __bfloat16_as_ushort(__float2bfloat16_rn(v.y)),
                   __bfloat16_as_ushort(__float2bfloat16_rn(v.z)),
                   __bfloat16_as_ushort(__float2bfloat16_rn(v.w))};
}
__global__ void split_res_kernel(int n4) {
    int i = blockIdx.x * blockDim.x + threadIdx.x;
    if (i < n4)
        reinterpret_cast<ushort4*>(g_rb)[i] =
            to_bf4(reinterpret_cast<const float4*>(g_res)[i]);
}
__global__ void split_cb_kernel(const float* __restrict__ cb, int n4) {
    int i = blockIdx.x * blockDim.x + threadIdx.x;
    if (i < n4)
        reinterpret_cast<ushort4*>(g_cbb)[i] =
            to_bf4(reinterpret_cast<const float4*>(cb)[i]);
}

// ---------------------------------------------------------------------------
// Coarse bf16 HMMA kernel. CTA: 128 tokens x 4096 codes (32 chunks of 128).
// 8 warps as 2(M) x 4(N); warp tile 64x32; K=256 per chunk.
#define C2S_OFF 0
#define A_OFF   16384
#define B_OFF   (16384 + 65536)
#define BUF_SZ  65536
#define SMEM_SZ (16384 + 65536 + 2 * 65536)

__global__ __launch_bounds__(256, 1)
void coarse_kernel(int layer) {
    extern __shared__ char smem[];
    const int tid  = threadIdx.x;
    const int lane = tid & 31, wid = tid >> 5;
    const int warpM = wid >> 2, warpN = wid & 3;
    const int tokbase = blockIdx.x * 128;

    const uint32_t sb   = smem_u32(smem);
    const uint32_t a_sm = sb + A_OFF;
    const uint32_t b_sm = sb + B_OFF;
    float* c2s = reinterpret_cast<float*>(smem);

    const __nv_bfloat16* cbB = g_cbb + (size_t)layer * K * D;

    // issue chunk 0 (cp.async)
    for (int i = tid; i < 4096; i += 256) {
        int r = i >> 5, c = i & 31;
        cp16(b_sm + r * 512 + ((c ^ (r & 7)) << 4), cbB + (size_t)r * D + c * 8);
    }
    asm volatile("cp.async.commit_group;");

    // A tile (resident) + c2 slice
    for (int i = tid; i < 4096; i += 256) {
        int r = i >> 5, c = i & 31;
        uint4 v = *reinterpret_cast<const uint4*>(
            g_rb + (size_t)(tokbase + r) * D + c * 8);
        *reinterpret_cast<uint4*>(smem + A_OFF + r * 512 + ((c ^ (r & 7)) << 4)) = v;
    }
    for (int i = tid; i < 1024; i += 256)
        reinterpret_cast<float4*>(smem)[i] =
            reinterpret_cast<const float4*>(g_c2 + layer * K)[i];

    // lane geometry for ldmatrix
    const int lrow  = ((lane >> 3) & 1) * 8 + (lane & 7);
    const int khalf = lane >> 4;
    uint32_t a_base[4]; int a_s7[4];
#pragma unroll
    for (int mi = 0; mi < 4; mi++) {
        int row = warpM * 64 + mi * 16 + lrow;
        a_base[mi] = a_sm + row * 512;
        a_s7[mi]   = row & 7;
    }
    uint32_t b_off[2]; int b_s7[2];
#pragma unroll
    for (int p = 0; p < 2; p++) {
        int row = warpN * 32 + p * 16 + lrow;
        b_off[p] = row * 512;
        b_s7[p]  = row & 7;
    }

    unsigned long long t0[8], t1[8];
#pragma unroll
    for (int s = 0; s < 8; s++) { t0[s] = ~0ull; t1[s] = ~0ull; }

    for (int ci = 0; ci < 32; ci++) {
        if (ci < 31) {
            const __nv_bfloat16* src = cbB + (size_t)(ci + 1) * 128 * D;
            uint32_t dstb = b_sm + ((ci + 1) & 1) * BUF_SZ;
            for (int i = tid; i < 4096; i += 256) {
                int r = i >> 5, c = i & 31;
                cp16(dstb + r * 512 + ((c ^ (r & 7)) << 4),
                     src + (size_t)r * D + c * 8);
            }
            asm volatile("cp.async.commit_group;");
            asm volatile("cp.async.wait_group 1;");
        } else {
            asm volatile("cp.async.wait_group 0;");
        }
        __syncthreads();

        const uint32_t bbase = b_sm + (ci & 1) * BUF_SZ;
        float acc[4][4][4];
#pragma unroll
        for (int mi = 0; mi < 4; mi++)
#pragma unroll
            for (int nt = 0; nt < 4; nt++)
#pragma unroll
                for (int v = 0; v < 4; v++) acc[mi][nt][v] = 0.f;

#pragma unroll
        for (int ks = 0; ks < 16; ks++) {
            const int c = ks * 2 + khalf;
            uint32_t a[4][4];
#pragma unroll
            for (int mi = 0; mi < 4; mi++)
                ldsm_x4(a[mi][0], a[mi][1], a[mi][2], a[mi][3],
                        a_base[mi] + ((c ^ a_s7[mi]) << 4));
            uint32_t b[4][2];
#pragma unroll
            for (int p = 0; p < 2; p++) {
                uint32_t r0, r1, r2, r3;
                ldsm_x4(r0, r1, r2, r3,
                        bbase + b_off[p] + ((c ^ b_s7[p]) << 4));
                b[p * 2][0]     = r0; b[p * 2][1]     = r2;
                b[p * 2 + 1][0] = r1; b[p * 2 + 1][1] = r3;
            }
#pragma unroll
            for (int mi = 0; mi < 4; mi++)
#pragma unroll
                for (int nt = 0; nt < 4; nt++)
                    mma16816(acc[mi][nt], a[mi], b[nt]);
        }

        // epilogue: scores -> running top-2 per token-row slot
        const int colbase = ci * 128 + warpN * 32 + 2 * (lane & 3);
#pragma unroll
        for (int nt = 0; nt < 4; nt++) {
            const int col = colbase + nt * 8;
            float2 c2v = *reinterpret_cast<const float2*>(c2s + col);
#pragma unroll
            for (int mi = 0; mi < 4; mi++)
#pragma unroll
                for (int h = 0; h < 2; h++) {
                    float s0 = fmaf(-2.f, acc[mi][nt][h * 2 + 0], c2v.x);
                    float s1 = fmaf(-2.f, acc[mi][nt][h * 2 + 1], c2v.y);
                    unsigned long long k0 = pack_key(s0, col);
                    unsigned long long k1 = pack_key(s1, col + 1);
                    const int s = mi * 2 + h;
                    if (k0 < t1[s]) {
                        if (k0 < t0[s]) { t1[s] = t0[s]; t0[s] = k0; }
                        else t1[s] = k0;
                    }
                    if (k1 < t1[s]) {
                        if (k1 < t0[s]) { t1[s] = t0[s]; t0[s] = k1; }
                        else t1[s] = k1;
                    }
                }
        }
        __syncthreads();
    }

    // quad merge (lanes sharing the same token rows) and store 2 cands/warp
#pragma unroll
    for (int s = 0; s < 8; s++) {
        unsigned long long a0 = t0[s], a1 = t1[s];
#pragma unroll
        for (int o = 1; o <= 2; o <<= 1) {
            unsigned long long q0 = __shfl_xor_sync(0xFFFFFFFFu, a0, o);
            unsigned long long q1 = __shfl_xor_sync(0xFFFFFFFFu, a1, o);
            unsigned long long m0 = a0 < q0 ? a0 : q0;
            unsigned long long mx = a0 < q0 ? q0 : a0;
            unsigned long long mn = a1 < q1 ? a1 : q1;
            a0 = m0;
            a1 = mx < mn ? mx : mn;
        }
        if ((lane & 3) == 0) {
            int token = tokbase + warpM * 64 + (s >> 1) * 16 + (s & 1) * 8 + (lane >> 2);
            g_cand[(size_t)token * 8 + warpN * 2]     = a0;
            g_cand[(size_t)token * 8 + warpN * 2 + 1] = a1;
        }
    }
}

// ---------------------------------------------------------------------------
// Exact fp32 rescore of the 8 coarse candidates. One warp per token.
__global__ void rescore_kernel(const float* __restrict__ cb, int layer, int n_tok) {
    int token = blockIdx.x * 8 + (threadIdx.x >> 5);
    int lane  = threadIdx.x & 31;
    if (token >= n_tok) return;
    unsigned mycode = (unsigned)(g_cand[(size_t)token * 8 + (lane & 7)] & 0xFFFFFFFFull);

    const float* r = g_res + (size_t)token * D + lane * 8;
    float4 r0 = *reinterpret_cast<const float4*>(r);
    float4 r1 = *reinterpret_cast<const float4*>(r + 4);

    const float* cbL = cb + (size_t)layer * K * D;
    unsigned long long best = ~0ull;
#pragma unroll
    for (int t = 0; t < 8; t++) {
        int code = (int)__shfl_sync(0xFFFFFFFFu, mycode, t);
        const float* c = cbL + (size_t)code * D + lane * 8;
        float4 c0 = *reinterpret_cast<const float4*>(c);
        float4 c1 = *reinterpret_cast<const float4*>(c + 4);
        float dot = r0.x * c0.x;
        dot = fmaf(r0.y, c0.y, dot); dot = fmaf(r0.z, c0.z, dot);
        dot = fmaf(r0.w, c0.w, dot); dot = fmaf(r1.x, c1.x, dot);
        dot = fmaf(r1.y, c1.y, dot); dot = fmaf(r1.z, c1.z, dot);
        dot = fmaf(r1.w, c1.w, dot);
#pragma unroll
        for (int o = 16; o; o >>= 1) dot += __shfl_xor_sync(0xFFFFFFFFu, dot, o);
        float score = fmaf(-2.f, dot, g_c2[layer * K + code]);
        unsigned long long key = pack_key(score, code);
        best = key < best ? key : best;
    }
    if (!lane) g_best[token] = best;
}

// ---------------------------------------------------------------------------
__global__ void update_kernel(const float* __restrict__ cb,
                              float* __restrict__ out,
                              int layer, int n_tok, int idx_base) {
    int token = blockIdx.x * 8 + (threadIdx.x >> 5);
    int lane  = threadIdx.x & 31;
    if (token >= n_tok) return;
    int idx = (int)(unsigned)(g_best[token] & 0xFFFFFFFFull);
    const float* q = cb + ((size_t)layer * K + idx) * D;
    float* r = g_res + (size_t)token * D;
    float local = 0.f;
#pragma unroll
    for (int t = 0; t < 2; t++) {
        int d = lane * 4 + t * 128;
        float4 rv = *reinterpret_cast<float4*>(r + d);
        float4 qv = *reinterpret_cast<const float4*>(q + d);
        rv.x -= qv.x; rv.y -= qv.y; rv.z -= qv.z; rv.w -= qv.w;
        local += rv.x * rv.x + rv.y * rv.y + rv.z * rv.z + rv.w * rv.w;
        *reinterpret_cast<float4*>(r + d) = rv;
    }
#pragma unroll
    for (int o = 16; o; o >>= 1) local += __shfl_down_sync(0xFFFFFFFFu, local, o);
    if (!lane) {
        out[idx_base + layer * n_tok + token] = (float)idx;
        atomicAdd(&g_loss[layer], local);
    }
}

// ---------------------------------------------------------------------------
__global__ void finalize_kernel(const float* __restrict__ x,
                                float* __restrict__ out,
                                int nx4, int loss_off, float invND) {
    int i = blockIdx.x * blockDim.x + threadIdx.x;
    if (i < nx4) {
        float4 xv = reinterpret_cast<const float4*>(x)[i];
        float4 rv = reinterpret_cast<const float4*>(g_res)[i];
        float4 o;
        o.x = xv.x - rv.x; o.y = xv.y - rv.y;
        o.z = xv.z - rv.z; o.w = xv.w - rv.w;
        reinterpret_cast<float4*>(out)[i] = o;
    }
    if (blockIdx.x == 0 && threadIdx.x < Q)
        out[loss_off + threadIdx.x] = g_loss[threadIdx.x] * invND;
}

// ---------------------------------------------------------------------------
extern "C" void kernel_launch(void* const* d_in, const int* in_sizes, int n_in,
                              void* d_out, int out_size) {
    const float* x  = (const float*)d_in[0];   // [8, 4096, 256] fp32
    const float* cb = (const float*)d_in[1];   // [4, 4096, 256] fp32
    float* out = (float*)d_out;

    int nx    = in_sizes[0];      // 8388608
    int n_tok = nx / D;           // 32768
    int nx4   = nx / 4;

    cudaFuncSetAttribute(coarse_kernel,
                         cudaFuncAttributeMaxDynamicSharedMemorySize, SMEM_SZ);

    copy_res_kernel<<<(nx4 + 255) / 256, 256>>>(x, nx4);
    c2_kernel<<<(Q * K) / 8, 256>>>(cb);
    split_cb_kernel<<<(CB_ELEMS / 4 + 255) / 256, 256>>>(cb, CB_ELEMS / 4);

    for (int qi = 0; qi < Q; qi++) {
        split_res_kernel<<<(nx4 + 255) / 256, 256>>>(nx4);
        coarse_kernel<<<n_tok / 128, 256, SMEM_SZ>>>(qi);
        rescore_kernel<<<n_tok / 8, 256>>>(cb, qi, n_tok);
        update_kernel<<<n_tok / 8, 256>>>(cb, out, qi, n_tok, nx);
    }

    finalize_kernel<<<(nx4 + 255) / 256, 256>>>(
        x, out, nx4, nx + Q * n_tok, 1.f / (float)nx);
}

// round 5
// speedup vs baseline: 4.2691x; 1.1705x over previous
#include <cuda_runtime.h>
#include <cuda_bf16.h>
#include <cstdint>

#define Q  4
#define K  4096
#define D  256
#define NTOK_MAX 32768
#define NX_MAX   (NTOK_MAX * D)
#define CB_ELEMS (Q * K * D)
#define SCORE_OFFSET 1024.0f

// ---------------- device scratch (allocation-free rule) ----------------
__device__ float               g_res[NX_MAX];         // residual [N, D] fp32
__device__ __nv_bfloat16       g_rb[NX_MAX];          // residual bf16
__device__ __nv_bfloat16       g_cbb[CB_ELEMS];       // codebook bf16
__device__ float               g_c2[Q * K];           // exact ||c||^2
__device__ unsigned            g_cand[NTOK_MAX * 8];  // 8 coarse cand codes/token
__device__ float               g_loss[Q];

// ---------------- helpers ----------------
__device__ __forceinline__ uint32_t smem_u32(const void* p) {
    uint32_t a;
    asm("{ .reg .u64 t; cvta.to.shared.u64 t, %1; cvt.u32.u64 %0, t; }"
        : "=r"(a) : "l"(p));
    return a;
}
__device__ __forceinline__ unsigned long long pack_key(float s, int code) {
    unsigned u = __float_as_uint(s);
    u = (u & 0x80000000u) ? ~u : (u | 0x80000000u);   // orderable fp32
    return ((unsigned long long)u << 32) | (unsigned)code;
}
__device__ __forceinline__ void cp16(uint32_t dst, const void* src) {
    asm volatile("cp.async.cg.shared.global [%0], [%1], 16;"
                 :: "r"(dst), "l"(src));
}
__device__ __forceinline__ void ldsm_x4(uint32_t& r0, uint32_t& r1,
                                        uint32_t& r2, uint32_t& r3, uint32_t a) {
    asm volatile("ldmatrix.sync.aligned.m8n8.x4.shared.b16 {%0,%1,%2,%3}, [%4];"
                 : "=r"(r0), "=r"(r1), "=r"(r2), "=r"(r3) : "r"(a));
}
__device__ __forceinline__ void mma16816(float* d, const uint32_t* a,
                                         const uint32_t* b) {
    asm volatile(
        "mma.sync.aligned.m16n8k16.row.col.f32.bf16.bf16.f32 "
        "{%0,%1,%2,%3},{%4,%5,%6,%7},{%8,%9},{%0,%1,%2,%3};"
        : "+f"(d[0]), "+f"(d[1]), "+f"(d[2]), "+f"(d[3])
        : "r"(a[0]), "r"(a[1]), "r"(a[2]), "r"(a[3]), "r"(b[0]), "r"(b[1]));
}
__device__ __forceinline__ ushort4 to_bf4(float4 v) {
    return ushort4{__bfloat16_as_ushort(__float2bfloat16_rn(v.x)),
                   __bfloat16_as_ushort(__float2bfloat16_rn(v.y)),
                   __bfloat16_as_ushort(__float2bfloat16_rn(v.z)),
                   __bfloat16_as_ushort(__float2bfloat16_rn(v.w))};
}
// exact-key top-2 insert with id tracking (~8 ops)
__device__ __forceinline__ void ins2(unsigned k, unsigned id,
                                     unsigned& t0, unsigned& i0,
                                     unsigned& t1, unsigned& i1) {
    bool p0 = k < t0;
    bool p1 = k < t1;
    unsigned nt1 = p1 ? k  : t1;
    unsigned ni1 = p1 ? id : i1;
    t1 = p0 ? t0 : nt1;
    i1 = p0 ? i0 : ni1;
    t0 = p0 ? k  : t0;
    i0 = p0 ? id : i0;
}

// ---------------------------------------------------------------------------
// residual = x (fp32 + bf16 mirror)
__global__ void copy_res_kernel(const float* __restrict__ x, int nx4) {
    int i = blockIdx.x * blockDim.x + threadIdx.x;
    if (i < nx4) {
        float4 v = reinterpret_cast<const float4*>(x)[i];
        reinterpret_cast<float4*>(g_res)[i] = v;
        reinterpret_cast<ushort4*>(g_rb)[i] = to_bf4(v);
    }
}

// exact ||c||^2 and zero losses
__global__ void c2_kernel(const float* __restrict__ cb) {
    if (blockIdx.x == 0 && threadIdx.x < Q) g_loss[threadIdx.x] = 0.f;
    int row  = blockIdx.x * 8 + (threadIdx.x >> 5);
    int lane = threadIdx.x & 31;
    const float* p = cb + (size_t)row * D;
    float s = 0.f;
#pragma unroll
    for (int t = 0; t < 2; t++) {
        float4 v = *reinterpret_cast<const float4*>(p + lane * 4 + t * 128);
        s += v.x * v.x + v.y * v.y + v.z * v.z + v.w * v.w;
    }
#pragma unroll
    for (int o = 16; o; o >>= 1) s += __shfl_down_sync(0xFFFFFFFFu, s, o);
    if (!lane) g_c2[row] = s;
}

__global__ void split_cb_kernel(const float* __restrict__ cb, int n4) {
    int i = blockIdx.x * blockDim.x + threadIdx.x;
    if (i < n4)
        reinterpret_cast<ushort4*>(g_cbb)[i] =
            to_bf4(reinterpret_cast<const float4*>(cb)[i]);
}

// ---------------------------------------------------------------------------
// Coarse bf16 HMMA kernel. CTA: 128 tokens x 4096 codes (32 chunks of 128).
// 8 warps as 2(M) x 4(N); warp tile 64x32; K=256 per chunk.
#define A_OFF   16384
#define B_OFF   (16384 + 65536)
#define BUF_SZ  65536
#define SMEM_SZ (16384 + 65536 + 2 * 65536)

__global__ __launch_bounds__(256, 1)
void coarse_kernel(int layer) {
    extern __shared__ char smem[];
    const int tid  = threadIdx.x;
    const int lane = tid & 31, wid = tid >> 5;
    const int warpM = wid >> 2, warpN = wid & 3;
    const int tokbase = blockIdx.x * 128;

    const uint32_t sb   = smem_u32(smem);
    const uint32_t a_sm = sb + A_OFF;
    const uint32_t b_sm = sb + B_OFF;
    float* c2s = reinterpret_cast<float*>(smem);

    const __nv_bfloat16* cbB = g_cbb + (size_t)layer * K * D;

    // issue chunk 0 (cp.async)
    for (int i = tid; i < 4096; i += 256) {
        int r = i >> 5, c = i & 31;
        cp16(b_sm + r * 512 + ((c ^ (r & 7)) << 4), cbB + (size_t)r * D + c * 8);
    }
    asm volatile("cp.async.commit_group;");

    // A tile (resident) + offset ||c||^2 slice (offset keeps scores positive,
    // so raw fp32 bits are u32-orderable)
    for (int i = tid; i < 4096; i += 256) {
        int r = i >> 5, c = i & 31;
        uint4 v = *reinterpret_cast<const uint4*>(
            g_rb + (size_t)(tokbase + r) * D + c * 8);
        *reinterpret_cast<uint4*>(smem + A_OFF + r * 512 + ((c ^ (r & 7)) << 4)) = v;
    }
    for (int i = tid; i < 4096; i += 256)
        c2s[i] = g_c2[layer * K + i] + SCORE_OFFSET;

    // lane geometry for ldmatrix
    const int lrow  = ((lane >> 3) & 1) * 8 + (lane & 7);
    const int khalf = lane >> 4;
    uint32_t a_base[4]; int a_s7[4];
#pragma unroll
    for (int mi = 0; mi < 4; mi++) {
        int row = warpM * 64 + mi * 16 + lrow;
        a_base[mi] = a_sm + row * 512;
        a_s7[mi]   = row & 7;
    }
    uint32_t b_off[2]; int b_s7[2];
#pragma unroll
    for (int p = 0; p < 2; p++) {
        int row = warpN * 32 + p * 16 + lrow;
        b_off[p] = row * 512;
        b_s7[p]  = row & 7;
    }

    // running top-2 (exact fp32-bit keys) + code ids, per token-row slot
    unsigned t0[8], t1[8], i0[8], i1[8];
#pragma unroll
    for (int s = 0; s < 8; s++) {
        t0[s] = 0xFFFFFFFFu; t1[s] = 0xFFFFFFFFu; i0[s] = 0u; i1[s] = 0u;
    }

    for (int ci = 0; ci < 32; ci++) {
        if (ci < 31) {
            const __nv_bfloat16* src = cbB + (size_t)(ci + 1) * 128 * D;
            uint32_t dstb = b_sm + ((ci + 1) & 1) * BUF_SZ;
            for (int i = tid; i < 4096; i += 256) {
                int r = i >> 5, c = i & 31;
                cp16(dstb + r * 512 + ((c ^ (r & 7)) << 4),
                     src + (size_t)r * D + c * 8);
            }
            asm volatile("cp.async.commit_group;");
            asm volatile("cp.async.wait_group 1;");
        } else {
            asm volatile("cp.async.wait_group 0;");
        }
        __syncthreads();

        const uint32_t bbase = b_sm + (ci & 1) * BUF_SZ;
        float acc[4][4][4];
#pragma unroll
        for (int mi = 0; mi < 4; mi++)
#pragma unroll
            for (int nt = 0; nt < 4; nt++)
#pragma unroll
                for (int v = 0; v < 4; v++) acc[mi][nt][v] = 0.f;

#pragma unroll
        for (int ks = 0; ks < 16; ks++) {
            const int c = ks * 2 + khalf;
            uint32_t a[4][4];
#pragma unroll
            for (int mi = 0; mi < 4; mi++)
                ldsm_x4(a[mi][0], a[mi][1], a[mi][2], a[mi][3],
                        a_base[mi] + ((c ^ a_s7[mi]) << 4));
            uint32_t b[4][2];
#pragma unroll
            for (int p = 0; p < 2; p++) {
                uint32_t r0, r1, r2, r3;
                ldsm_x4(r0, r1, r2, r3,
                        bbase + b_off[p] + ((c ^ b_s7[p]) << 4));
                b[p * 2][0]     = r0; b[p * 2][1]     = r2;
                b[p * 2 + 1][0] = r1; b[p * 2 + 1][1] = r3;
            }
#pragma unroll
            for (int mi = 0; mi < 4; mi++)
#pragma unroll
                for (int nt = 0; nt < 4; nt++)
                    mma16816(acc[mi][nt], a[mi], b[nt]);
        }

        // epilogue: exact-key top-2 (~9 ops/candidate incl. FFMA)
        const int innerbase = 2 * (lane & 3);
#pragma unroll
        for (int nt = 0; nt < 4; nt++) {
            const int col = ci * 128 + warpN * 32 + innerbase + nt * 8;
            float2 c2v = *reinterpret_cast<const float2*>(c2s + col);
#pragma unroll
            for (int mi = 0; mi < 4; mi++)
#pragma unroll
                for (int h = 0; h < 2; h++) {
                    float s0 = fmaf(-2.f, acc[mi][nt][h * 2 + 0], c2v.x);
                    float s1 = fmaf(-2.f, acc[mi][nt][h * 2 + 1], c2v.y);
                    const int s = mi * 2 + h;
                    ins2(__float_as_uint(s0), (unsigned)col,
                         t0[s], i0[s], t1[s], i1[s]);
                    ins2(__float_as_uint(s1), (unsigned)(col + 1),
                         t0[s], i0[s], t1[s], i1[s]);
                }
        }
        __syncthreads();
    }

    // quad merge (lanes sharing the same token rows) and store 2 cands/warp
#pragma unroll
    for (int s = 0; s < 8; s++) {
        unsigned a0 = t0[s], b0 = i0[s], a1 = t1[s], b1 = i1[s];
#pragma unroll
        for (int o = 1; o <= 2; o <<= 1) {
            unsigned q0  = __shfl_xor_sync(0xFFFFFFFFu, a0, o);
            unsigned qi0 = __shfl_xor_sync(0xFFFFFFFFu, b0, o);
            unsigned q1  = __shfl_xor_sync(0xFFFFFFFFu, a1, o);
            unsigned qi1 = __shfl_xor_sync(0xFFFFFFFFu, b1, o);
            ins2(q0, qi0, a0, b0, a1, b1);
            ins2(q1, qi1, a0, b0, a1, b1);
        }
        if ((lane & 3) == 0) {
            int token = tokbase + warpM * 64 + (s >> 1) * 16 + (s & 1) * 8 + (lane >> 2);
            g_cand[(size_t)token * 8 + warpN * 2]     = b0;
            g_cand[(size_t)token * 8 + warpN * 2 + 1] = b1;
        }
    }
}

// ---------------------------------------------------------------------------
// Fused: exact fp32 rescore of 8 candidates + residual update + bf16 mirror +
// index output + commit loss. One warp per token.
__global__ void rescore_update_kernel(const float* __restrict__ cb,
                                      float* __restrict__ out,
                                      int layer, int n_tok, int idx_base) {
    int token = blockIdx.x * 8 + (threadIdx.x >> 5);
    int lane  = threadIdx.x & 31;
    if (token >= n_tok) return;
    unsigned mycode = g_cand[(size_t)token * 8 + (lane & 7)];

    float* rp = g_res + (size_t)token * D + lane * 8;
    float4 r0 = *reinterpret_cast<const float4*>(rp);
    float4 r1 = *reinterpret_cast<const float4*>(rp + 4);

    const float* cbL = cb + (size_t)layer * K * D;
    unsigned long long best = ~0ull;
#pragma unroll
    for (int t = 0; t < 8; t++) {
        int code = (int)__shfl_sync(0xFFFFFFFFu, mycode, t);
        const float* c = cbL + (size_t)code * D + lane * 8;
        float4 c0 = *reinterpret_cast<const float4*>(c);
        float4 c1 = *reinterpret_cast<const float4*>(c + 4);
        float dot = r0.x * c0.x;
        dot = fmaf(r0.y, c0.y, dot); dot = fmaf(r0.z, c0.z, dot);
        dot = fmaf(r0.w, c0.w, dot); dot = fmaf(r1.x, c1.x, dot);
        dot = fmaf(r1.y, c1.y, dot); dot = fmaf(r1.z, c1.z, dot);
        dot = fmaf(r1.w, c1.w, dot);
#pragma unroll
        for (int o = 16; o; o >>= 1) dot += __shfl_xor_sync(0xFFFFFFFFu, dot, o);
        float score = fmaf(-2.f, dot, g_c2[layer * K + code]);
        unsigned long long key = pack_key(score, code);
        best = key < best ? key : best;
    }
    int idx = (int)(unsigned)(best & 0xFFFFFFFFull);

    // update: residual -= codeword; write fp32 + bf16; loss
    const float* q = cbL + (size_t)idx * D + lane * 8;
    float4 q0 = *reinterpret_cast<const float4*>(q);
    float4 q1 = *reinterpret_cast<const float4*>(q + 4);
    r0.x -= q0.x; r0.y -= q0.y; r0.z -= q0.z; r0.w -= q0.w;
    r1.x -= q1.x; r1.y -= q1.y; r1.z -= q1.z; r1.w -= q1.w;
    *reinterpret_cast<float4*>(rp)     = r0;
    *reinterpret_cast<float4*>(rp + 4) = r1;
    ushort4* bp = reinterpret_cast<ushort4*>(g_rb + (size_t)token * D + lane * 8);
    bp[0] = to_bf4(r0);
    bp[1] = to_bf4(r1);
    float local = r0.x * r0.x + r0.y * r0.y + r0.z * r0.z + r0.w * r0.w
                + r1.x * r1.x + r1.y * r1.y + r1.z * r1.z + r1.w * r1.w;
#pragma unroll
    for (int o = 16; o; o >>= 1) local += __shfl_down_sync(0xFFFFFFFFu, local, o);
    if (!lane) {
        out[idx_base + layer * n_tok + token] = (float)idx;
        atomicAdd(&g_loss[layer], local);
    }
}

// ---------------------------------------------------------------------------
__global__ void finalize_kernel(const float* __restrict__ x,
                                float* __restrict__ out,
                                int nx4, int loss_off, float invND) {
    int i = blockIdx.x * blockDim.x + threadIdx.x;
    if (i < nx4) {
        float4 xv = reinterpret_cast<const float4*>(x)[i];
        float4 rv = reinterpret_cast<const float4*>(g_res)[i];
        float4 o;
        o.x = xv.x - rv.x; o.y = xv.y - rv.y;
        o.z = xv.z - rv.z; o.w = xv.w - rv.w;
        reinterpret_cast<float4*>(out)[i] = o;
    }
    if (blockIdx.x == 0 && threadIdx.x < Q)
        out[loss_off + threadIdx.x] = g_loss[threadIdx.x] * invND;
}

// ---------------------------------------------------------------------------
extern "C" void kernel_launch(void* const* d_in, const int* in_sizes, int n_in,
                              void* d_out, int out_size) {
    const float* x  = (const float*)d_in[0];   // [8, 4096, 256] fp32
    const float* cb = (const float*)d_in[1];   // [4, 4096, 256] fp32
    float* out = (float*)d_out;

    int nx    = in_sizes[0];      // 8388608
    int n_tok = nx / D;           // 32768
    int nx4   = nx / 4;

    cudaFuncSetAttribute(coarse_kernel,
                         cudaFuncAttributeMaxDynamicSharedMemorySize, SMEM_SZ);

    copy_res_kernel<<<(nx4 + 255) / 256, 256>>>(x, nx4);
    c2_kernel<<<(Q * K) / 8, 256>>>(cb);
    split_cb_kernel<<<(CB_ELEMS / 4 + 255) / 256, 256>>>(cb, CB_ELEMS / 4);

    for (int qi = 0; qi < Q; qi++) {
        coarse_kernel<<<n_tok / 128, 256, SMEM_SZ>>>(qi);
        rescore_update_kernel<<<n_tok / 8, 256>>>(cb, out, qi, n_tok, nx);
    }

    finalize_kernel<<<(nx4 + 255) / 256, 256>>>(
        x, out, nx4, nx + Q * n_tok, 1.f / (float)nx);
}

// round 6
// speedup vs baseline: 4.4880x; 1.0513x over previous
#include <cuda_runtime.h>
#include <cuda_bf16.h>
#include <cstdint>

#define Q  4
#define K  4096
#define D  256
#define NTOK_MAX 32768
#define NX_MAX   (NTOK_MAX * D)
#define CB_ELEMS (Q * K * D)
#define SCORE_OFFSET 1024.0f

// ---------------- device scratch (allocation-free rule) ----------------
__device__ float               g_res[NX_MAX];         // residual [N, D] fp32
__device__ __nv_bfloat16       g_rb[NX_MAX];          // residual bf16
__device__ __nv_bfloat16       g_cbb[CB_ELEMS];       // codebook bf16
__device__ float               g_c2[Q * K];           // exact ||c||^2
__device__ unsigned            g_cand[NTOK_MAX * 8];  // 8 coarse cand codes/token
__device__ float               g_loss[Q];

// ---------------- helpers ----------------
__device__ __forceinline__ uint32_t smem_u32(const void* p) {
    uint32_t a;
    asm("{ .reg .u64 t; cvta.to.shared.u64 t, %1; cvt.u32.u64 %0, t; }"
        : "=r"(a) : "l"(p));
    return a;
}
__device__ __forceinline__ unsigned long long pack_key(float s, int code) {
    unsigned u = __float_as_uint(s);
    u = (u & 0x80000000u) ? ~u : (u | 0x80000000u);   // orderable fp32
    return ((unsigned long long)u << 32) | (unsigned)code;
}
__device__ __forceinline__ void cp16(uint32_t dst, const void* src) {
    asm volatile("cp.async.cg.shared.global [%0], [%1], 16;"
                 :: "r"(dst), "l"(src));
}
__device__ __forceinline__ void ldsm_x4(uint32_t& r0, uint32_t& r1,
                                        uint32_t& r2, uint32_t& r3, uint32_t a) {
    asm volatile("ldmatrix.sync.aligned.m8n8.x4.shared.b16 {%0,%1,%2,%3}, [%4];"
                 : "=r"(r0), "=r"(r1), "=r"(r2), "=r"(r3) : "r"(a));
}
__device__ __forceinline__ void mma16816(float* d, const uint32_t* a,
                                         const uint32_t* b) {
    asm volatile(
        "mma.sync.aligned.m16n8k16.row.col.f32.bf16.bf16.f32 "
        "{%0,%1,%2,%3},{%4,%5,%6,%7},{%8,%9},{%0,%1,%2,%3};"
        : "+f"(d[0]), "+f"(d[1]), "+f"(d[2]), "+f"(d[3])
        : "r"(a[0]), "r"(a[1]), "r"(a[2]), "r"(a[3]), "r"(b[0]), "r"(b[1]));
}
__device__ __forceinline__ ushort4 to_bf4(float4 v) {
    return ushort4{__bfloat16_as_ushort(__float2bfloat16_rn(v.x)),
                   __bfloat16_as_ushort(__float2bfloat16_rn(v.y)),
                   __bfloat16_as_ushort(__float2bfloat16_rn(v.z)),
                   __bfloat16_as_ushort(__float2bfloat16_rn(v.w))};
}
// exact-key top-2 insert with id tracking (~8 ops)
__device__ __forceinline__ void ins2(unsigned k, unsigned id,
                                     unsigned& t0, unsigned& i0,
                                     unsigned& t1, unsigned& i1) {
    bool p0 = k < t0;
    bool p1 = k < t1;
    unsigned nt1 = p1 ? k  : t1;
    unsigned ni1 = p1 ? id : i1;
    t1 = p0 ? t0 : nt1;
    i1 = p0 ? i0 : ni1;
    t0 = p0 ? k  : t0;
    i0 = p0 ? id : i0;
}

// ---------------------------------------------------------------------------
// residual = x (fp32 + bf16 mirror)
__global__ void copy_res_kernel(const float* __restrict__ x, int nx4) {
    int i = blockIdx.x * blockDim.x + threadIdx.x;
    if (i < nx4) {
        float4 v = reinterpret_cast<const float4*>(x)[i];
        reinterpret_cast<float4*>(g_res)[i] = v;
        reinterpret_cast<ushort4*>(g_rb)[i] = to_bf4(v);
    }
}

// exact ||c||^2 and zero losses
__global__ void c2_kernel(const float* __restrict__ cb) {
    if (blockIdx.x == 0 && threadIdx.x < Q) g_loss[threadIdx.x] = 0.f;
    int row  = blockIdx.x * 8 + (threadIdx.x >> 5);
    int lane = threadIdx.x & 31;
    const float* p = cb + (size_t)row * D;
    float s = 0.f;
#pragma unroll
    for (int t = 0; t < 2; t++) {
        float4 v = *reinterpret_cast<const float4*>(p + lane * 4 + t * 128);
        s += v.x * v.x + v.y * v.y + v.z * v.z + v.w * v.w;
    }
#pragma unroll
    for (int o = 16; o; o >>= 1) s += __shfl_down_sync(0xFFFFFFFFu, s, o);
    if (!lane) g_c2[row] = s;
}

__global__ void split_cb_kernel(const float* __restrict__ cb, int n4) {
    int i = blockIdx.x * blockDim.x + threadIdx.x;
    if (i < n4)
        reinterpret_cast<ushort4*>(g_cbb)[i] =
            to_bf4(reinterpret_cast<const float4*>(cb)[i]);
}

// ---------------------------------------------------------------------------
// Coarse bf16 HMMA kernel. CTA: 128 tokens x 4096 codes (32 chunks of 128).
// 16 warps as 4(M) x 4(N); warp tile 32x32; K=256 per chunk.
#define A_OFF   16384
#define B_OFF   (16384 + 65536)
#define BUF_SZ  65536
#define SMEM_SZ (16384 + 65536 + 2 * 65536)
#define CTHREADS 512

__global__ __launch_bounds__(CTHREADS, 1)
void coarse_kernel(int layer) {
    extern __shared__ char smem[];
    const int tid  = threadIdx.x;
    const int lane = tid & 31, wid = tid >> 5;
    const int warpM = wid >> 2, warpN = wid & 3;
    const int tokbase = blockIdx.x * 128;

    const uint32_t sb   = smem_u32(smem);
    const uint32_t a_sm = sb + A_OFF;
    const uint32_t b_sm = sb + B_OFF;
    float* c2s = reinterpret_cast<float*>(smem);

    const __nv_bfloat16* cbB = g_cbb + (size_t)layer * K * D;

    // issue chunk 0 (cp.async)
    for (int i = tid; i < 4096; i += CTHREADS) {
        int r = i >> 5, c = i & 31;
        cp16(b_sm + r * 512 + ((c ^ (r & 7)) << 4), cbB + (size_t)r * D + c * 8);
    }
    asm volatile("cp.async.commit_group;");

    // A tile (resident) + offset ||c||^2 slice (offset keeps scores positive,
    // so raw fp32 bits are u32-orderable)
    for (int i = tid; i < 4096; i += CTHREADS) {
        int r = i >> 5, c = i & 31;
        uint4 v = *reinterpret_cast<const uint4*>(
            g_rb + (size_t)(tokbase + r) * D + c * 8);
        *reinterpret_cast<uint4*>(smem + A_OFF + r * 512 + ((c ^ (r & 7)) << 4)) = v;
    }
    for (int i = tid; i < 4096; i += CTHREADS)
        c2s[i] = g_c2[layer * K + i] + SCORE_OFFSET;

    // lane geometry for ldmatrix
    const int lrow  = ((lane >> 3) & 1) * 8 + (lane & 7);
    const int khalf = lane >> 4;
    uint32_t a_base[2]; int a_s7[2];
#pragma unroll
    for (int mi = 0; mi < 2; mi++) {
        int row = warpM * 32 + mi * 16 + lrow;
        a_base[mi] = a_sm + row * 512;
        a_s7[mi]   = row & 7;
    }
    uint32_t b_off[2]; int b_s7[2];
#pragma unroll
    for (int p = 0; p < 2; p++) {
        int row = warpN * 32 + p * 16 + lrow;
        b_off[p] = row * 512;
        b_s7[p]  = row & 7;
    }

    // running top-2 (exact fp32-bit keys) + code ids, per token-row slot
    unsigned t0[4], t1[4], i0[4], i1[4];
#pragma unroll
    for (int s = 0; s < 4; s++) {
        t0[s] = 0xFFFFFFFFu; t1[s] = 0xFFFFFFFFu; i0[s] = 0u; i1[s] = 0u;
    }

    for (int ci = 0; ci < 32; ci++) {
        if (ci < 31) {
            const __nv_bfloat16* src = cbB + (size_t)(ci + 1) * 128 * D;
            uint32_t dstb = b_sm + ((ci + 1) & 1) * BUF_SZ;
            for (int i = tid; i < 4096; i += CTHREADS) {
                int r = i >> 5, c = i & 31;
                cp16(dstb + r * 512 + ((c ^ (r & 7)) << 4),
                     src + (size_t)r * D + c * 8);
            }
            asm volatile("cp.async.commit_group;");
            asm volatile("cp.async.wait_group 1;");
        } else {
            asm volatile("cp.async.wait_group 0;");
        }
        __syncthreads();

        const uint32_t bbase = b_sm + (ci & 1) * BUF_SZ;
        float acc[2][4][4];
#pragma unroll
        for (int mi = 0; mi < 2; mi++)
#pragma unroll
            for (int nt = 0; nt < 4; nt++)
#pragma unroll
                for (int v = 0; v < 4; v++) acc[mi][nt][v] = 0.f;

#pragma unroll
        for (int ks = 0; ks < 16; ks++) {
            const int c = ks * 2 + khalf;
            uint32_t a[2][4];
#pragma unroll
            for (int mi = 0; mi < 2; mi++)
                ldsm_x4(a[mi][0], a[mi][1], a[mi][2], a[mi][3],
                        a_base[mi] + ((c ^ a_s7[mi]) << 4));
            uint32_t b[4][2];
#pragma unroll
            for (int p = 0; p < 2; p++) {
                uint32_t r0, r1, r2, r3;
                ldsm_x4(r0, r1, r2, r3,
                        bbase + b_off[p] + ((c ^ b_s7[p]) << 4));
                b[p * 2][0]     = r0; b[p * 2][1]     = r2;
                b[p * 2 + 1][0] = r1; b[p * 2 + 1][1] = r3;
            }
#pragma unroll
            for (int mi = 0; mi < 2; mi++)
#pragma unroll
                for (int nt = 0; nt < 4; nt++)
                    mma16816(acc[mi][nt], a[mi], b[nt]);
        }

        // epilogue: exact-key top-2 (~9 ops/candidate incl. FFMA)
        const int innerbase = 2 * (lane & 3);
#pragma unroll
        for (int nt = 0; nt < 4; nt++) {
            const int col = ci * 128 + warpN * 32 + innerbase + nt * 8;
            float2 c2v = *reinterpret_cast<const float2*>(c2s + col);
#pragma unroll
            for (int mi = 0; mi < 2; mi++)
#pragma unroll
                for (int h = 0; h < 2; h++) {
                    float s0 = fmaf(-2.f, acc[mi][nt][h * 2 + 0], c2v.x);
                    float s1 = fmaf(-2.f, acc[mi][nt][h * 2 + 1], c2v.y);
                    const int s = mi * 2 + h;
                    ins2(__float_as_uint(s0), (unsigned)col,
                         t0[s], i0[s], t1[s], i1[s]);
                    ins2(__float_as_uint(s1), (unsigned)(col + 1),
                         t0[s], i0[s], t1[s], i1[s]);
                }
        }
        __syncthreads();
    }

    // quad merge (lanes sharing the same token rows) and store 2 cands/warp
#pragma unroll
    for (int s = 0; s < 4; s++) {
        unsigned a0 = t0[s], b0 = i0[s], a1 = t1[s], b1 = i1[s];
#pragma unroll
        for (int o = 1; o <= 2; o <<= 1) {
            unsigned q0  = __shfl_xor_sync(0xFFFFFFFFu, a0, o);
            unsigned qi0 = __shfl_xor_sync(0xFFFFFFFFu, b0, o);
            unsigned q1  = __shfl_xor_sync(0xFFFFFFFFu, a1, o);
            unsigned qi1 = __shfl_xor_sync(0xFFFFFFFFu, b1, o);
            ins2(q0, qi0, a0, b0, a1, b1);
            ins2(q1, qi1, a0, b0, a1, b1);
        }
        if ((lane & 3) == 0) {
            int token = tokbase + warpM * 32 + (s >> 1) * 16 + (s & 1) * 8 + (lane >> 2);
            g_cand[(size_t)token * 8 + warpN * 2]     = b0;
            g_cand[(size_t)token * 8 + warpN * 2 + 1] = b1;
        }
    }
}

// ---------------------------------------------------------------------------
// Fused: exact fp32 rescore of 8 candidates + residual update + bf16 mirror +
// index output + commit loss. One warp per token.
__global__ void rescore_update_kernel(const float* __restrict__ cb,
                                      float* __restrict__ out,
                                      int layer, int n_tok, int idx_base) {
    int token = blockIdx.x * 8 + (threadIdx.x >> 5);
    int lane  = threadIdx.x & 31;
    if (token >= n_tok) return;
    unsigned mycode = g_cand[(size_t)token * 8 + (lane & 7)];

    float* rp = g_res + (size_t)token * D + lane * 8;
    float4 r0 = *reinterpret_cast<const float4*>(rp);
    float4 r1 = *reinterpret_cast<const float4*>(rp + 4);

    const float* cbL = cb + (size_t)layer * K * D;
    unsigned long long best = ~0ull;
#pragma unroll
    for (int t = 0; t < 8; t++) {
        int code = (int)__shfl_sync(0xFFFFFFFFu, mycode, t);
        const float* c = cbL + (size_t)code * D + lane * 8;
        float4 c0 = *reinterpret_cast<const float4*>(c);
        float4 c1 = *reinterpret_cast<const float4*>(c + 4);
        float dot = r0.x * c0.x;
        dot = fmaf(r0.y, c0.y, dot); dot = fmaf(r0.z, c0.z, dot);
        dot = fmaf(r0.w, c0.w, dot); dot = fmaf(r1.x, c1.x, dot);
        dot = fmaf(r1.y, c1.y, dot); dot = fmaf(r1.z, c1.z, dot);
        dot = fmaf(r1.w, c1.w, dot);
#pragma unroll
        for (int o = 16; o; o >>= 1) dot += __shfl_xor_sync(0xFFFFFFFFu, dot, o);
        float score = fmaf(-2.f, dot, g_c2[layer * K + code]);
        unsigned long long key = pack_key(score, code);
        best = key < best ? key : best;
    }
    int idx = (int)(unsigned)(best & 0xFFFFFFFFull);

    // update: residual -= codeword; write fp32 + bf16; loss
    const float* q = cbL + (size_t)idx * D + lane * 8;
    float4 q0 = *reinterpret_cast<const float4*>(q);
    float4 q1 = *reinterpret_cast<const float4*>(q + 4);
    r0.x -= q0.x; r0.y -= q0.y; r0.z -= q0.z; r0.w -= q0.w;
    r1.x -= q1.x; r1.y -= q1.y; r1.z -= q1.z; r1.w -= q1.w;
    *reinterpret_cast<float4*>(rp)     = r0;
    *reinterpret_cast<float4*>(rp + 4) = r1;
    ushort4* bp = reinterpret_cast<ushort4*>(g_rb + (size_t)token * D + lane * 8);
    bp[0] = to_bf4(r0);
    bp[1] = to_bf4(r1);
    float local = r0.x * r0.x + r0.y * r0.y + r0.z * r0.z + r0.w * r0.w
                + r1.x * r1.x + r1.y * r1.y + r1.z * r1.z + r1.w * r1.w;
#pragma unroll
    for (int o = 16; o; o >>= 1) local += __shfl_down_sync(0xFFFFFFFFu, local, o);
    if (!lane) {
        out[idx_base + layer * n_tok + token] = (float)idx;
        atomicAdd(&g_loss[layer], local);
    }
}

// ---------------------------------------------------------------------------
__global__ void finalize_kernel(const float* __restrict__ x,
                                float* __restrict__ out,
                                int nx4, int loss_off, float invND) {
    int i = blockIdx.x * blockDim.x + threadIdx.x;
    if (i < nx4) {
        float4 xv = reinterpret_cast<const float4*>(x)[i];
        float4 rv = reinterpret_cast<const float4*>(g_res)[i];
        float4 o;
        o.x = xv.x - rv.x; o.y = xv.y - rv.y;
        o.z = xv.z - rv.z; o.w = xv.w - rv.w;
        reinterpret_cast<float4*>(out)[i] = o;
    }
    if (blockIdx.x == 0 && threadIdx.x < Q)
        out[loss_off + threadIdx.x] = g_loss[threadIdx.x] * invND;
}

// ---------------------------------------------------------------------------
extern "C" void kernel_launch(void* const* d_in, const int* in_sizes, int n_in,
                              void* d_out, int out_size) {
    const float* x  = (const float*)d_in[0];   // [8, 4096, 256] fp32
    const float* cb = (const float*)d_in[1];   // [4, 4096, 256] fp32
    float* out = (float*)d_out;

    int nx    = in_sizes[0];      // 8388608
    int n_tok = nx / D;           // 32768
    int nx4   = nx / 4;

    cudaFuncSetAttribute(coarse_kernel,
                         cudaFuncAttributeMaxDynamicSharedMemorySize, SMEM_SZ);

    copy_res_kernel<<<(nx4 + 255) / 256, 256>>>(x, nx4);
    c2_kernel<<<(Q * K) / 8, 256>>>(cb);
    split_cb_kernel<<<(CB_ELEMS / 4 + 255) / 256, 256>>>(cb, CB_ELEMS / 4);

    for (int qi = 0; qi < Q; qi++) {
        coarse_kernel<<<n_tok / 128, CTHREADS, SMEM_SZ>>>(qi);
        rescore_update_kernel<<<n_tok / 8, 256>>>(cb, out, qi, n_tok, nx);
    }

    finalize_kernel<<<(nx4 + 255) / 256, 256>>>(
        x, out, nx4, nx + Q * n_tok, 1.f / (float)nx);
}

// round 8
// speedup vs baseline: 5.0318x; 1.1212x over previous
#include <cuda_runtime.h>
#include <cuda_bf16.h>
#include <cstdint>

#define Q  4
#define K  4096
#define D  256
#define NTOK_MAX 32768
#define NX_MAX   (NTOK_MAX * D)
#define CB_ELEMS (Q * K * D)
#define SCORE_OFFSET 1024.0f

// ---------------- device scratch (allocation-free rule) ----------------
__device__ float               g_res[NX_MAX];         // residual [N, D] fp32
__device__ __nv_bfloat16       g_rb[NX_MAX];          // residual bf16
__device__ __nv_bfloat16       g_cbb[CB_ELEMS];       // codebook bf16
__device__ float               g_c2[Q * K];           // exact ||c||^2
__device__ unsigned            g_cand[NTOK_MAX * 8];  // 8 coarse cand codes/token
__device__ float               g_loss[Q];

// ---------------- helpers ----------------
__device__ __forceinline__ uint32_t smem_u32(const void* p) {
    uint32_t a;
    asm("{ .reg .u64 t; cvta.to.shared.u64 t, %1; cvt.u32.u64 %0, t; }"
        : "=r"(a) : "l"(p));
    return a;
}
__device__ __forceinline__ unsigned long long pack_key(float s, int code) {
    unsigned u = __float_as_uint(s);
    u = (u & 0x80000000u) ? ~u : (u | 0x80000000u);   // orderable fp32
    return ((unsigned long long)u << 32) | (unsigned)code;
}
__device__ __forceinline__ void cp16(uint32_t dst, const void* src) {
    asm volatile("cp.async.cg.shared.global [%0], [%1], 16;"
                 :: "r"(dst), "l"(src));
}
__device__ __forceinline__ void mbar_init(uint32_t m, uint32_t cnt) {
    asm volatile("mbarrier.init.shared.b64 [%0], %1;" :: "r"(m), "r"(cnt) : "memory");
}
__device__ __forceinline__ void mbar_arrive(uint32_t m) {
    asm volatile("mbarrier.arrive.shared.b64 _, [%0];" :: "r"(m) : "memory");
}
// NOINC: does NOT raise the expected-arrival count — the barrier's preset
// count must equal the number of cp-arrive callers. (Default variant
// increments expectation and is net-neutral -> deadlocks this pattern.)
__device__ __forceinline__ void cp_arrive(uint32_t m) {
    asm volatile("cp.async.mbarrier.arrive.noinc.shared.b64 [%0];"
                 :: "r"(m) : "memory");
}
__device__ __forceinline__ void wait_parity(uint32_t m, uint32_t ph) {
    asm volatile(
        "{\n\t.reg .pred P;\n\t"
        "W%=:\n\t"
        "mbarrier.try_wait.parity.acquire.cta.shared::cta.b64 P, [%0], %1, 0x989680;\n\t"
        "@P bra D%=;\n\t"
        "bra W%=;\n\t"
        "D%=:\n\t}"
        :: "r"(m), "r"(ph) : "memory");
}
__device__ __forceinline__ void ldsm_x4(uint32_t& r0, uint32_t& r1,
                                        uint32_t& r2, uint32_t& r3, uint32_t a) {
    asm volatile("ldmatrix.sync.aligned.m8n8.x4.shared.b16 {%0,%1,%2,%3}, [%4];"
                 : "=r"(r0), "=r"(r1), "=r"(r2), "=r"(r3) : "r"(a));
}
__device__ __forceinline__ void mma16816(float* d, const uint32_t* a,
                                         const uint32_t* b) {
    asm volatile(
        "mma.sync.aligned.m16n8k16.row.col.f32.bf16.bf16.f32 "
        "{%0,%1,%2,%3},{%4,%5,%6,%7},{%8,%9},{%0,%1,%2,%3};"
        : "+f"(d[0]), "+f"(d[1]), "+f"(d[2]), "+f"(d[3])
        : "r"(a[0]), "r"(a[1]), "r"(a[2]), "r"(a[3]), "r"(b[0]), "r"(b[1]));
}
__device__ __forceinline__ ushort4 to_bf4(float4 v) {
    return ushort4{__bfloat16_as_ushort(__float2bfloat16_rn(v.x)),
                   __bfloat16_as_ushort(__float2bfloat16_rn(v.y)),
                   __bfloat16_as_ushort(__float2bfloat16_rn(v.z)),
                   __bfloat16_as_ushort(__float2bfloat16_rn(v.w))};
}
// float-key top-2 insert with id tracking; FMNMX/FSETP on fma pipe, SEL on alu
__device__ __forceinline__ void ins2f(float k, unsigned id,
                                      float& t0, unsigned& i0,
                                      float& t1, unsigned& i1) {
    bool p0 = k < t0;
    bool p1 = k < t1;
    float    nt1 = p1 ? k  : t1;
    unsigned ni1 = p1 ? id : i1;
    t1 = p0 ? t0 : nt1;
    i1 = p0 ? i0 : ni1;
    t0 = fminf(t0, k);
    i0 = p0 ? id : i0;
}

// ---------------------------------------------------------------------------
// residual = x (fp32 + bf16 mirror)
__global__ void copy_res_kernel(const float* __restrict__ x, int nx4) {
    int i = blockIdx.x * blockDim.x + threadIdx.x;
    if (i < nx4) {
        float4 v = reinterpret_cast<const float4*>(x)[i];
        reinterpret_cast<float4*>(g_res)[i] = v;
        reinterpret_cast<ushort4*>(g_rb)[i] = to_bf4(v);
    }
}

// exact ||c||^2 and zero losses
__global__ void c2_kernel(const float* __restrict__ cb) {
    if (blockIdx.x == 0 && threadIdx.x < Q) g_loss[threadIdx.x] = 0.f;
    int row  = blockIdx.x * 8 + (threadIdx.x >> 5);
    int lane = threadIdx.x & 31;
    const float* p = cb + (size_t)row * D;
    float s = 0.f;
#pragma unroll
    for (int t = 0; t < 2; t++) {
        float4 v = *reinterpret_cast<const float4*>(p + lane * 4 + t * 128);
        s += v.x * v.x + v.y * v.y + v.z * v.z + v.w * v.w;
    }
#pragma unroll
    for (int o = 16; o; o >>= 1) s += __shfl_down_sync(0xFFFFFFFFu, s, o);
    if (!lane) g_c2[row] = s;
}

__global__ void split_cb_kernel(const float* __restrict__ cb, int n4) {
    int i = blockIdx.x * blockDim.x + threadIdx.x;
    if (i < n4)
        reinterpret_cast<ushort4*>(g_cbb)[i] =
            to_bf4(reinterpret_cast<const float4*>(cb)[i]);
}

// ---------------------------------------------------------------------------
// Coarse bf16 HMMA kernel. CTA: 128 tokens x 4096 codes (32 chunks of 128).
// 16 warps as 4(M) x 4(N); warp tile 32x32; K=256 per chunk.
// mbarrier-pipelined: no CTA-wide barrier in the steady loop, so one warp's
// argmin epilogue (alu/fma) overlaps other warps' MMA (tensor).
#define A_OFF   16384
#define B_OFF   (16384 + 65536)
#define BUF_SZ  65536
#define MB_OFF  (B_OFF + 2 * BUF_SZ)
#define SMEM_SZ (MB_OFF + 64)
#define CTHREADS 512

__global__ __launch_bounds__(CTHREADS, 1)
void coarse_kernel(int layer) {
    extern __shared__ char smem[];
    const int tid  = threadIdx.x;
    const int lane = tid & 31, wid = tid >> 5;
    const int warpM = wid >> 2, warpN = wid & 3;
    const int tokbase = blockIdx.x * 128;

    const uint32_t sb   = smem_u32(smem);
    const uint32_t a_sm = sb + A_OFF;
    const uint32_t b_sm = sb + B_OFF;
    const uint32_t mb_fill  = sb + MB_OFF;        // 2 x 8B
    const uint32_t mb_drain = sb + MB_OFF + 16;   // 2 x 8B
    float* c2s = reinterpret_cast<float*>(smem);

    const __nv_bfloat16* cbB = g_cbb + (size_t)layer * K * D;

    if (tid == 0) {
        mbar_init(mb_fill,      CTHREADS);
        mbar_init(mb_fill + 8,  CTHREADS);
        mbar_init(mb_drain,     16);
        mbar_init(mb_drain + 8, 16);
    }
    __syncthreads();

    // prolog: issue chunks 0 and 1
#pragma unroll
    for (int pc = 0; pc < 2; pc++) {
        const __nv_bfloat16* src = cbB + (size_t)pc * 128 * D;
        uint32_t dstb = b_sm + pc * BUF_SZ;
        for (int i = tid; i < 4096; i += CTHREADS) {
            int r = i >> 5, c = i & 31;
            cp16(dstb + r * 512 + ((c ^ (r & 7)) << 4), src + (size_t)r * D + c * 8);
        }
        cp_arrive(mb_fill + pc * 8);
    }

    // A tile (resident) + offset ||c||^2 slice
    for (int i = tid; i < 4096; i += CTHREADS) {
        int r = i >> 5, c = i & 31;
        uint4 v = *reinterpret_cast<const uint4*>(
            g_rb + (size_t)(tokbase + r) * D + c * 8);
        *reinterpret_cast<uint4*>(smem + A_OFF + r * 512 + ((c ^ (r & 7)) << 4)) = v;
    }
    for (int i = tid; i < 4096; i += CTHREADS)
        c2s[i] = g_c2[layer * K + i] + SCORE_OFFSET;
    __syncthreads();   // A + c2s visible to all warps

    // lane geometry for ldmatrix
    const int lrow  = ((lane >> 3) & 1) * 8 + (lane & 7);
    const int khalf = lane >> 4;
    uint32_t a_base[2]; int a_s7[2];
#pragma unroll
    for (int mi = 0; mi < 2; mi++) {
        int row = warpM * 32 + mi * 16 + lrow;
        a_base[mi] = a_sm + row * 512;
        a_s7[mi]   = row & 7;
    }
    uint32_t b_off[2]; int b_s7[2];
#pragma unroll
    for (int p = 0; p < 2; p++) {
        int row = warpN * 32 + p * 16 + lrow;
        b_off[p] = row * 512;
        b_s7[p]  = row & 7;
    }

    // running top-2 (float keys) + code ids, per token-row slot
    float    t0[4], t1[4];
    unsigned i0[4], i1[4];
#pragma unroll
    for (int s = 0; s < 4; s++) {
        t0[s] = __int_as_float(0x7f800000);
        t1[s] = __int_as_float(0x7f800000);
        i0[s] = 0u; i1[s] = 0u;
    }

    for (int ci = 0; ci < 32; ci++) {
        const int b  = ci & 1;
        const uint32_t ph = (unsigned)((ci >> 1) & 1);

        wait_parity(mb_fill + b * 8, ph);          // chunk ci data visible

        const uint32_t bbase = b_sm + b * BUF_SZ;
        float acc[2][4][4];
#pragma unroll
        for (int mi = 0; mi < 2; mi++)
#pragma unroll
            for (int nt = 0; nt < 4; nt++)
#pragma unroll
                for (int v = 0; v < 4; v++) acc[mi][nt][v] = 0.f;

#pragma unroll
        for (int ks = 0; ks < 16; ks++) {
            const int c = ks * 2 + khalf;
            uint32_t a[2][4];
#pragma unroll
            for (int mi = 0; mi < 2; mi++)
                ldsm_x4(a[mi][0], a[mi][1], a[mi][2], a[mi][3],
                        a_base[mi] + ((c ^ a_s7[mi]) << 4));
            uint32_t b2[4][2];
#pragma unroll
            for (int p = 0; p < 2; p++) {
                uint32_t r0, r1, r2, r3;
                ldsm_x4(r0, r1, r2, r3,
                        bbase + b_off[p] + ((c ^ b_s7[p]) << 4));
                b2[p * 2][0]     = r0; b2[p * 2][1]     = r2;
                b2[p * 2 + 1][0] = r1; b2[p * 2 + 1][1] = r3;
            }
#pragma unroll
            for (int mi = 0; mi < 2; mi++)
#pragma unroll
                for (int nt = 0; nt < 4; nt++)
                    mma16816(acc[mi][nt], a[mi], b2[nt]);
        }
        if (lane == 0) mbar_arrive(mb_drain + b * 8);   // my reads of buf b done

        // epilogue: float-key top-2 (overlaps other warps' MMA)
        const int innerbase = 2 * (lane & 3);
#pragma unroll
        for (int nt = 0; nt < 4; nt++) {
            const int col = ci * 128 + warpN * 32 + innerbase + nt * 8;
            float2 c2v = *reinterpret_cast<const float2*>(c2s + col);
#pragma unroll
            for (int mi = 0; mi < 2; mi++)
#pragma unroll
                for (int h = 0; h < 2; h++) {
                    float s0 = fmaf(-2.f, acc[mi][nt][h * 2 + 0], c2v.x);
                    float s1 = fmaf(-2.f, acc[mi][nt][h * 2 + 1], c2v.y);
                    const int s = mi * 2 + h;
                    ins2f(s0, (unsigned)col,       t0[s], i0[s], t1[s], i1[s]);
                    ins2f(s1, (unsigned)(col + 1), t0[s], i0[s], t1[s], i1[s]);
                }
        }

        if (ci < 30) {
            wait_parity(mb_drain + b * 8, ph);     // all warps done reading buf b
            const __nv_bfloat16* src = cbB + (size_t)(ci + 2) * 128 * D;
            uint32_t dstb = b_sm + b * BUF_SZ;
            for (int i = tid; i < 4096; i += CTHREADS) {
                int r = i >> 5, c = i & 31;
                cp16(dstb + r * 512 + ((c ^ (r & 7)) << 4),
                     src + (size_t)r * D + c * 8);
            }
            cp_arrive(mb_fill + b * 8);
        }
    }

    // quad merge (lanes sharing the same token rows) and store 2 cands/warp
#pragma unroll
    for (int s = 0; s < 4; s++) {
        float    a0 = t0[s], a1 = t1[s];
        unsigned b0 = i0[s], b1 = i1[s];
#pragma unroll
        for (int o = 1; o <= 2; o <<= 1) {
            float    q0  = __shfl_xor_sync(0xFFFFFFFFu, a0, o);
            unsigned qi0 = __shfl_xor_sync(0xFFFFFFFFu, b0, o);
            float    q1  = __shfl_xor_sync(0xFFFFFFFFu, a1, o);
            unsigned qi1 = __shfl_xor_sync(0xFFFFFFFFu, b1, o);
            ins2f(q0, qi0, a0, b0, a1, b1);
            ins2f(q1, qi1, a0, b0, a1, b1);
        }
        if ((lane & 3) == 0) {
            int token = tokbase + warpM * 32 + (s >> 1) * 16 + (s & 1) * 8 + (lane >> 2);
            g_cand[(size_t)token * 8 + warpN * 2]     = b0;
            g_cand[(size_t)token * 8 + warpN * 2 + 1] = b1;
        }
    }
}

// ---------------------------------------------------------------------------
// Fused: exact fp32 rescore of 8 candidates + residual update + bf16 mirror +
// index output + commit loss. One warp per token.
__global__ void rescore_update_kernel(const float* __restrict__ cb,
                                      float* __restrict__ out,
                                      int layer, int n_tok, int idx_base) {
    int token = blockIdx.x * 8 + (threadIdx.x >> 5);
    int lane  = threadIdx.x & 31;
    if (token >= n_tok) return;
    unsigned mycode = g_cand[(size_t)token * 8 + (lane & 7)];

    float* rp = g_res + (size_t)token * D + lane * 8;
    float4 r0 = *reinterpret_cast<const float4*>(rp);
    float4 r1 = *reinterpret_cast<const float4*>(rp + 4);

    const float* cbL = cb + (size_t)layer * K * D;
    unsigned long long best = ~0ull;
#pragma unroll
    for (int t = 0; t < 8; t++) {
        int code = (int)__shfl_sync(0xFFFFFFFFu, mycode, t);
        const float* c = cbL + (size_t)code * D + lane * 8;
        float4 c0 = *reinterpret_cast<const float4*>(c);
        float4 c1 = *reinterpret_cast<const float4*>(c + 4);
        float dot = r0.x * c0.x;
        dot = fmaf(r0.y, c0.y, dot); dot = fmaf(r0.z, c0.z, dot);
        dot = fmaf(r0.w, c0.w, dot); dot = fmaf(r1.x, c1.x, dot);
        dot = fmaf(r1.y, c1.y, dot); dot = fmaf(r1.z, c1.z, dot);
        dot = fmaf(r1.w, c1.w, dot);
#pragma unroll
        for (int o = 16; o; o >>= 1) dot += __shfl_xor_sync(0xFFFFFFFFu, dot, o);
        float score = fmaf(-2.f, dot, g_c2[layer * K + code]);
        unsigned long long key = pack_key(score, code);
        best = key < best ? key : best;
    }
    int idx = (int)(unsigned)(best & 0xFFFFFFFFull);

    // update: residual -= codeword; write fp32 + bf16; loss
    const float* q = cbL + (size_t)idx * D + lane * 8;
    float4 q0 = *reinterpret_cast<const float4*>(q);
    float4 q1 = *reinterpret_cast<const float4*>(q + 4);
    r0.x -= q0.x; r0.y -= q0.y; r0.z -= q0.z; r0.w -= q0.w;
    r1.x -= q1.x; r1.y -= q1.y; r1.z -= q1.z; r1.w -= q1.w;
    *reinterpret_cast<float4*>(rp)     = r0;
    *reinterpret_cast<float4*>(rp + 4) = r1;
    ushort4* bp = reinterpret_cast<ushort4*>(g_rb + (size_t)token * D + lane * 8);
    bp[0] = to_bf4(r0);
    bp[1] = to_bf4(r1);
    float local = r0.x * r0.x + r0.y * r0.y + r0.z * r0.z + r0.w * r0.w
                + r1.x * r1.x + r1.y * r1.y + r1.z * r1.z + r1.w * r1.w;
#pragma unroll
    for (int o = 16; o; o >>= 1) local += __shfl_down_sync(0xFFFFFFFFu, local, o);
    if (!lane) {
        out[idx_base + layer * n_tok + token] = (float)idx;
        atomicAdd(&g_loss[layer], local);
    }
}

// ---------------------------------------------------------------------------
__global__ void finalize_kernel(const float* __restrict__ x,
                                float* __restrict__ out,
                                int nx4, int loss_off, float invND) {
    int i = blockIdx.x * blockDim.x + threadIdx.x;
    if (i < nx4) {
        float4 xv = reinterpret_cast<const float4*>(x)[i];
        float4 rv = reinterpret_cast<const float4*>(g_res)[i];
        float4 o;
        o.x = xv.x - rv.x; o.y = xv.y - rv.y;
        o.z = xv.z - rv.z; o.w = xv.w - rv.w;
        reinterpret_cast<float4*>(out)[i] = o;
    }
    if (blockIdx.x == 0 && threadIdx.x < Q)
        out[loss_off + threadIdx.x] = g_loss[threadIdx.x] * invND;
}

// ---------------------------------------------------------------------------
extern "C" void kernel_launch(void* const* d_in, const int* in_sizes, int n_in,
                              void* d_out, int out_size) {
    const float* x  = (const float*)d_in[0];   // [8, 4096, 256] fp32
    const float* cb = (const float*)d_in[1];   // [4, 4096, 256] fp32
    float* out = (float*)d_out;

    int nx    = in_sizes[0];      // 8388608
    int n_tok = nx / D;           // 32768
    int nx4   = nx / 4;

    cudaFuncSetAttribute(coarse_kernel,
                         cudaFuncAttributeMaxDynamicSharedMemorySize, SMEM_SZ);

    copy_res_kernel<<<(nx4 + 255) / 256, 256>>>(x, nx4);
    c2_kernel<<<(Q * K) / 8, 256>>>(cb);
    split_cb_kernel<<<(CB_ELEMS / 4 + 255) / 256, 256>>>(cb, CB_ELEMS / 4);

    for (int qi = 0; qi < Q; qi++) {
        coarse_kernel<<<n_tok / 128, CTHREADS, SMEM_SZ>>>(qi);
        rescore_update_kernel<<<n_tok / 8, 256>>>(cb, out, qi, n_tok, nx);
    }

    finalize_kernel<<<(nx4 + 255) / 256, 256>>>(
        x, out, nx4, nx + Q * n_tok, 1.f / (float)nx);
}

// round 9
// speedup vs baseline: 5.0781x; 1.0092x over previous
#include <cuda_runtime.h>
#include <cuda_bf16.h>
#include <cstdint>

#define Q  4
#define K  4096
#define D  256
#define NTOK_MAX 32768
#define NX_MAX   (NTOK_MAX * D)
#define CB_ELEMS (Q * K * D)
#define SCORE_OFFSET 1024.0f

// ---------------- device scratch (allocation-free rule) ----------------
__device__ float               g_res[NX_MAX];         // residual [N, D] fp32
__device__ __nv_bfloat16       g_rb[NX_MAX];          // residual bf16
__device__ __nv_bfloat16       g_cbb[CB_ELEMS];       // codebook bf16
__device__ float               g_c2[Q * K];           // exact ||c||^2
__device__ float               g_loss[Q];

// ---------------- helpers ----------------
__device__ __forceinline__ uint32_t smem_u32(const void* p) {
    uint32_t a;
    asm("{ .reg .u64 t; cvta.to.shared.u64 t, %1; cvt.u32.u64 %0, t; }"
        : "=r"(a) : "l"(p));
    return a;
}
__device__ __forceinline__ unsigned long long pack_key(float s, int code) {
    unsigned u = __float_as_uint(s);
    u = (u & 0x80000000u) ? ~u : (u | 0x80000000u);   // orderable fp32
    return ((unsigned long long)u << 32) | (unsigned)code;
}
__device__ __forceinline__ void cp16(uint32_t dst, const void* src) {
    asm volatile("cp.async.cg.shared.global [%0], [%1], 16;"
                 :: "r"(dst), "l"(src));
}
__device__ __forceinline__ void mbar_init(uint32_t m, uint32_t cnt) {
    asm volatile("mbarrier.init.shared.b64 [%0], %1;" :: "r"(m), "r"(cnt) : "memory");
}
__device__ __forceinline__ void mbar_arrive(uint32_t m) {
    asm volatile("mbarrier.arrive.shared.b64 _, [%0];" :: "r"(m) : "memory");
}
// NOINC: barrier count must equal the number of cp-arrive callers.
__device__ __forceinline__ void cp_arrive(uint32_t m) {
    asm volatile("cp.async.mbarrier.arrive.noinc.shared.b64 [%0];"
                 :: "r"(m) : "memory");
}
__device__ __forceinline__ void wait_parity(uint32_t m, uint32_t ph) {
    asm volatile(
        "{\n\t.reg .pred P;\n\t"
        "W%=:\n\t"
        "mbarrier.try_wait.parity.acquire.cta.shared::cta.b64 P, [%0], %1, 0x989680;\n\t"
        "@P bra D%=;\n\t"
        "bra W%=;\n\t"
        "D%=:\n\t}"
        :: "r"(m), "r"(ph) : "memory");
}
__device__ __forceinline__ void ldsm_x4(uint32_t& r0, uint32_t& r1,
                                        uint32_t& r2, uint32_t& r3, uint32_t a) {
    asm volatile("ldmatrix.sync.aligned.m8n8.x4.shared.b16 {%0,%1,%2,%3}, [%4];"
                 : "=r"(r0), "=r"(r1), "=r"(r2), "=r"(r3) : "r"(a));
}
__device__ __forceinline__ void mma16816(float* d, const uint32_t* a,
                                         const uint32_t* b) {
    asm volatile(
        "mma.sync.aligned.m16n8k16.row.col.f32.bf16.bf16.f32 "
        "{%0,%1,%2,%3},{%4,%5,%6,%7},{%8,%9},{%0,%1,%2,%3};"
        : "+f"(d[0]), "+f"(d[1]), "+f"(d[2]), "+f"(d[3])
        : "r"(a[0]), "r"(a[1]), "r"(a[2]), "r"(a[3]), "r"(b[0]), "r"(b[1]));
}
__device__ __forceinline__ ushort4 to_bf4(float4 v) {
    return ushort4{__bfloat16_as_ushort(__float2bfloat16_rn(v.x)),
                   __bfloat16_as_ushort(__float2bfloat16_rn(v.y)),
                   __bfloat16_as_ushort(__float2bfloat16_rn(v.z)),
                   __bfloat16_as_ushort(__float2bfloat16_rn(v.w))};
}
// float-key top-2 insert with id tracking; FMNMX/FSETP on fma pipe, SEL on alu
__device__ __forceinline__ void ins2f(float k, unsigned id,
                                      float& t0, unsigned& i0,
                                      float& t1, unsigned& i1) {
    bool p0 = k < t0;
    bool p1 = k < t1;
    float    nt1 = p1 ? k  : t1;
    unsigned ni1 = p1 ? id : i1;
    t1 = p0 ? t0 : nt1;
    i1 = p0 ? i0 : ni1;
    t0 = fminf(t0, k);
    i0 = p0 ? id : i0;
}

// ---------------------------------------------------------------------------
// residual = x (fp32 + bf16 mirror)
__global__ void copy_res_kernel(const float* __restrict__ x, int nx4) {
    int i = blockIdx.x * blockDim.x + threadIdx.x;
    if (i < nx4) {
        float4 v = reinterpret_cast<const float4*>(x)[i];
        reinterpret_cast<float4*>(g_res)[i] = v;
        reinterpret_cast<ushort4*>(g_rb)[i] = to_bf4(v);
    }
}

// exact ||c||^2 and zero losses
__global__ void c2_kernel(const float* __restrict__ cb) {
    if (blockIdx.x == 0 && threadIdx.x < Q) g_loss[threadIdx.x] = 0.f;
    int row  = blockIdx.x * 8 + (threadIdx.x >> 5);
    int lane = threadIdx.x & 31;
    const float* p = cb + (size_t)row * D;
    float s = 0.f;
#pragma unroll
    for (int t = 0; t < 2; t++) {
        float4 v = *reinterpret_cast<const float4*>(p + lane * 4 + t * 128);
        s += v.x * v.x + v.y * v.y + v.z * v.z + v.w * v.w;
    }
#pragma unroll
    for (int o = 16; o; o >>= 1) s += __shfl_down_sync(0xFFFFFFFFu, s, o);
    if (!lane) g_c2[row] = s;
}

__global__ void split_cb_kernel(const float* __restrict__ cb, int n4) {
    int i = blockIdx.x * blockDim.x + threadIdx.x;
    if (i < n4)
        reinterpret_cast<ushort4*>(g_cbb)[i] =
            to_bf4(reinterpret_cast<const float4*>(cb)[i]);
}

// ---------------------------------------------------------------------------
// Fused coarse + rescore + update kernel.
// Phase 1 (coarse): bf16 HMMA, CTA = 128 tokens x 4096 codes (32 chunks),
//   16 warps 4(M)x4(N), warp tile 32x32, mbarrier double-buffer pipeline,
//   per-token top-2 per warpN group -> 8 candidates/token in smem.
// Phase 2 (fused tail): exact fp32 rescore of the 8 candidates, residual
//   update + bf16 mirror + index + loss. Overlaps other CTAs' phase 1.
#define A_OFF    16384
#define B_OFF    (16384 + 65536)
#define BUF_SZ   65536
#define MB_OFF   (B_OFF + 2 * BUF_SZ)
#define CAND_OFF (MB_OFF + 64)
#define LOSS_OFF (CAND_OFF + 128 * 8 * 4)
#define SMEM_SZ  (LOSS_OFF + 128 * 4)
#define CTHREADS 512

__global__ __launch_bounds__(CTHREADS, 1)
void coarse_kernel(const float* __restrict__ cbF, float* __restrict__ out,
                   int layer, int n_tok, int idx_base) {
    extern __shared__ char smem[];
    const int tid  = threadIdx.x;
    const int lane = tid & 31, wid = tid >> 5;
    const int warpM = wid >> 2, warpN = wid & 3;
    const int tokbase = blockIdx.x * 128;

    const uint32_t sb   = smem_u32(smem);
    const uint32_t a_sm = sb + A_OFF;
    const uint32_t b_sm = sb + B_OFF;
    const uint32_t mb_fill  = sb + MB_OFF;        // 2 x 8B
    const uint32_t mb_drain = sb + MB_OFF + 16;   // 2 x 8B
    float*    c2s     = reinterpret_cast<float*>(smem);
    unsigned* cand_sm = reinterpret_cast<unsigned*>(smem + CAND_OFF);
    float*    loss_sm = reinterpret_cast<float*>(smem + LOSS_OFF);

    const __nv_bfloat16* cbB = g_cbb + (size_t)layer * K * D;

    if (tid == 0) {
        mbar_init(mb_fill,      CTHREADS);
        mbar_init(mb_fill + 8,  CTHREADS);
        mbar_init(mb_drain,     16);
        mbar_init(mb_drain + 8, 16);
    }
    __syncthreads();

    // prolog: issue chunks 0 and 1
#pragma unroll
    for (int pc = 0; pc < 2; pc++) {
        const __nv_bfloat16* src = cbB + (size_t)pc * 128 * D;
        uint32_t dstb = b_sm + pc * BUF_SZ;
        for (int i = tid; i < 4096; i += CTHREADS) {
            int r = i >> 5, c = i & 31;
            cp16(dstb + r * 512 + ((c ^ (r & 7)) << 4), src + (size_t)r * D + c * 8);
        }
        cp_arrive(mb_fill + pc * 8);
    }

    // A tile (resident) + offset ||c||^2 slice
    for (int i = tid; i < 4096; i += CTHREADS) {
        int r = i >> 5, c = i & 31;
        uint4 v = *reinterpret_cast<const uint4*>(
            g_rb + (size_t)(tokbase + r) * D + c * 8);
        *reinterpret_cast<uint4*>(smem + A_OFF + r * 512 + ((c ^ (r & 7)) << 4)) = v;
    }
    for (int i = tid; i < 4096; i += CTHREADS)
        c2s[i] = g_c2[layer * K + i] + SCORE_OFFSET;
    __syncthreads();   // A + c2s visible to all warps

    // lane geometry for ldmatrix
    const int lrow  = ((lane >> 3) & 1) * 8 + (lane & 7);
    const int khalf = lane >> 4;
    uint32_t a_base[2]; int a_s7[2];
#pragma unroll
    for (int mi = 0; mi < 2; mi++) {
        int row = warpM * 32 + mi * 16 + lrow;
        a_base[mi] = a_sm + row * 512;
        a_s7[mi]   = row & 7;
    }
    uint32_t b_off[2]; int b_s7[2];
#pragma unroll
    for (int p = 0; p < 2; p++) {
        int row = warpN * 32 + p * 16 + lrow;
        b_off[p] = row * 512;
        b_s7[p]  = row & 7;
    }

    // running top-2 (float keys) + code ids, per token-row slot
    float    t0[4], t1[4];
    unsigned i0[4], i1[4];
#pragma unroll
    for (int s = 0; s < 4; s++) {
        t0[s] = __int_as_float(0x7f800000);
        t1[s] = __int_as_float(0x7f800000);
        i0[s] = 0u; i1[s] = 0u;
    }

    for (int ci = 0; ci < 32; ci++) {
        const int b  = ci & 1;
        const uint32_t ph = (unsigned)((ci >> 1) & 1);

        wait_parity(mb_fill + b * 8, ph);          // chunk ci data visible

        const uint32_t bbase = b_sm + b * BUF_SZ;
        float acc[2][4][4];
#pragma unroll
        for (int mi = 0; mi < 2; mi++)
#pragma unroll
            for (int nt = 0; nt < 4; nt++)
#pragma unroll
                for (int v = 0; v < 4; v++) acc[mi][nt][v] = 0.f;

#pragma unroll
        for (int ks = 0; ks < 16; ks++) {
            const int c = ks * 2 + khalf;
            uint32_t a[2][4];
#pragma unroll
            for (int mi = 0; mi < 2; mi++)
                ldsm_x4(a[mi][0], a[mi][1], a[mi][2], a[mi][3],
                        a_base[mi] + ((c ^ a_s7[mi]) << 4));
            uint32_t b2[4][2];
#pragma unroll
            for (int p = 0; p < 2; p++) {
                uint32_t r0, r1, r2, r3;
                ldsm_x4(r0, r1, r2, r3,
                        bbase + b_off[p] + ((c ^ b_s7[p]) << 4));
                b2[p * 2][0]     = r0; b2[p * 2][1]     = r2;
                b2[p * 2 + 1][0] = r1; b2[p * 2 + 1][1] = r3;
            }
#pragma unroll
            for (int mi = 0; mi < 2; mi++)
#pragma unroll
                for (int nt = 0; nt < 4; nt++)
                    mma16816(acc[mi][nt], a[mi], b2[nt]);
        }
        if (lane == 0) mbar_arrive(mb_drain + b * 8);   // my reads of buf b done

        // epilogue: float-key top-2 (overlaps other warps' MMA)
        const int innerbase = 2 * (lane & 3);
#pragma unroll
        for (int nt = 0; nt < 4; nt++) {
            const int col = ci * 128 + warpN * 32 + innerbase + nt * 8;
            float2 c2v = *reinterpret_cast<const float2*>(c2s + col);
#pragma unroll
            for (int mi = 0; mi < 2; mi++)
#pragma unroll
                for (int h = 0; h < 2; h++) {
                    float s0 = fmaf(-2.f, acc[mi][nt][h * 2 + 0], c2v.x);
                    float s1 = fmaf(-2.f, acc[mi][nt][h * 2 + 1], c2v.y);
                    const int s = mi * 2 + h;
                    ins2f(s0, (unsigned)col,       t0[s], i0[s], t1[s], i1[s]);
                    ins2f(s1, (unsigned)(col + 1), t0[s], i0[s], t1[s], i1[s]);
                }
        }

        if (ci < 30) {
            wait_parity(mb_drain + b * 8, ph);     // all warps done reading buf b
            const __nv_bfloat16* src = cbB + (size_t)(ci + 2) * 128 * D;
            uint32_t dstb = b_sm + b * BUF_SZ;
            for (int i = tid; i < 4096; i += CTHREADS) {
                int r = i >> 5, c = i & 31;
                cp16(dstb + r * 512 + ((c ^ (r & 7)) << 4),
                     src + (size_t)r * D + c * 8);
            }
            cp_arrive(mb_fill + b * 8);
        }
    }

    // quad merge (lanes sharing the same token rows); 2 candidates per warpN
    // group per token staged into smem
#pragma unroll
    for (int s = 0; s < 4; s++) {
        float    a0 = t0[s], a1 = t1[s];
        unsigned b0 = i0[s], b1 = i1[s];
#pragma unroll
        for (int o = 1; o <= 2; o <<= 1) {
            float    q0  = __shfl_xor_sync(0xFFFFFFFFu, a0, o);
            unsigned qi0 = __shfl_xor_sync(0xFFFFFFFFu, b0, o);
            float    q1  = __shfl_xor_sync(0xFFFFFFFFu, a1, o);
            unsigned qi1 = __shfl_xor_sync(0xFFFFFFFFu, b1, o);
            ins2f(q0, qi0, a0, b0, a1, b1);
            ins2f(q1, qi1, a0, b0, a1, b1);
        }
        if ((lane & 3) == 0) {
            int ltok = warpM * 32 + (s >> 1) * 16 + (s & 1) * 8 + (lane >> 2);
            cand_sm[ltok * 8 + warpN * 2]     = b0;
            cand_sm[ltok * 8 + warpN * 2 + 1] = b1;
        }
    }
    __syncthreads();

    // -------- fused tail: exact fp32 rescore + update, warp w -> 8 tokens ---
    const float* cbL = cbF + (size_t)layer * K * D;
#pragma unroll 1
    for (int tt = 0; tt < 8; tt++) {
        const int ltok  = wid * 8 + tt;
        const int token = tokbase + ltok;
        unsigned mycode = cand_sm[ltok * 8 + (lane & 7)];

        float* rp = g_res + (size_t)token * D + lane * 8;
        float4 r0 = *reinterpret_cast<const float4*>(rp);
        float4 r1 = *reinterpret_cast<const float4*>(rp + 4);

        unsigned long long best = ~0ull;
#pragma unroll 1
        for (int t = 0; t < 8; t++) {
            int code = (int)__shfl_sync(0xFFFFFFFFu, mycode, t);
            const float* c = cbL + (size_t)code * D + lane * 8;
            float4 c0 = *reinterpret_cast<const float4*>(c);
            float4 c1 = *reinterpret_cast<const float4*>(c + 4);
            float dot = r0.x * c0.x;
            dot = fmaf(r0.y, c0.y, dot); dot = fmaf(r0.z, c0.z, dot);
            dot = fmaf(r0.w, c0.w, dot); dot = fmaf(r1.x, c1.x, dot);
            dot = fmaf(r1.y, c1.y, dot); dot = fmaf(r1.z, c1.z, dot);
            dot = fmaf(r1.w, c1.w, dot);
#pragma unroll
            for (int o = 16; o; o >>= 1)
                dot += __shfl_xor_sync(0xFFFFFFFFu, dot, o);
            float score = fmaf(-2.f, dot, g_c2[layer * K + code]);  // exact c2
            unsigned long long key = pack_key(score, code);
            best = key < best ? key : best;
        }
        int idx = (int)(unsigned)(best & 0xFFFFFFFFull);

        // update: residual -= codeword; write fp32 (+ bf16 unless last layer)
        const float* q = cbL + (size_t)idx * D + lane * 8;
        float4 q0 = *reinterpret_cast<const float4*>(q);
        float4 q1 = *reinterpret_cast<const float4*>(q + 4);
        r0.x -= q0.x; r0.y -= q0.y; r0.z -= q0.z; r0.w -= q0.w;
        r1.x -= q1.x; r1.y -= q1.y; r1.z -= q1.z; r1.w -= q1.w;
        *reinterpret_cast<float4*>(rp)     = r0;
        *reinterpret_cast<float4*>(rp + 4) = r1;
        if (layer < Q - 1) {
            ushort4* bp = reinterpret_cast<ushort4*>(
                g_rb + (size_t)token * D + lane * 8);
            bp[0] = to_bf4(r0);
            bp[1] = to_bf4(r1);
        }
        float local = r0.x * r0.x + r0.y * r0.y + r0.z * r0.z + r0.w * r0.w
                    + r1.x * r1.x + r1.y * r1.y + r1.z * r1.z + r1.w * r1.w;
#pragma unroll
        for (int o = 16; o; o >>= 1)
            local += __shfl_down_sync(0xFFFFFFFFu, local, o);
        if (!lane) {
            out[idx_base + layer * n_tok + token] = (float)idx;
            loss_sm[ltok] = local;
        }
    }
    __syncthreads();
    if (wid == 0) {
        float s = loss_sm[lane] + loss_sm[lane + 32]
                + loss_sm[lane + 64] + loss_sm[lane + 96];
#pragma unroll
        for (int o = 16; o; o >>= 1) s += __shfl_down_sync(0xFFFFFFFFu, s, o);
        if (!lane) atomicAdd(&g_loss[layer], s);
    }
}

// ---------------------------------------------------------------------------
__global__ void finalize_kernel(const float* __restrict__ x,
                                float* __restrict__ out,
                                int nx4, int loss_off, float invND) {
    int i = blockIdx.x * blockDim.x + threadIdx.x;
    if (i < nx4) {
        float4 xv = reinterpret_cast<const float4*>(x)[i];
        float4 rv = reinterpret_cast<const float4*>(g_res)[i];
        float4 o;
        o.x = xv.x - rv.x; o.y = xv.y - rv.y;
        o.z = xv.z - rv.z; o.w = xv.w - rv.w;
        reinterpret_cast<float4*>(out)[i] = o;
    }
    if (blockIdx.x == 0 && threadIdx.x < Q)
        out[loss_off + threadIdx.x] = g_loss[threadIdx.x] * invND;
}

// ---------------------------------------------------------------------------
extern "C" void kernel_launch(void* const* d_in, const int* in_sizes, int n_in,
                              void* d_out, int out_size) {
    const float* x  = (const float*)d_in[0];   // [8, 4096, 256] fp32
    const float* cb = (const float*)d_in[1];   // [4, 4096, 256] fp32
    float* out = (float*)d_out;

    int nx    = in_sizes[0];      // 8388608
    int n_tok = nx / D;           // 32768
    int nx4   = nx / 4;

    cudaFuncSetAttribute(coarse_kernel,
                         cudaFuncAttributeMaxDynamicSharedMemorySize, SMEM_SZ);

    copy_res_kernel<<<(nx4 + 255) / 256, 256>>>(x, nx4);
    c2_kernel<<<(Q * K) / 8, 256>>>(cb);
    split_cb_kernel<<<(CB_ELEMS / 4 + 255) / 256, 256>>>(cb, CB_ELEMS / 4);

    for (int qi = 0; qi < Q; qi++)
        coarse_kernel<<<n_tok / 128, CTHREADS, SMEM_SZ>>>(cb, out, qi, n_tok, nx);

    finalize_kernel<<<(nx4 + 255) / 256, 256>>>(
        x, out, nx4, nx + Q * n_tok, 1.f / (float)nx);
}

// round 10
// speedup vs baseline: 5.4039x; 1.0642x over previous
#include <cuda_runtime.h>
#include <cuda_bf16.h>
#include <cstdint>

#define Q  4
#define K  4096
#define D  256
#define NTOK_MAX 32768
#define NX_MAX   (NTOK_MAX * D)
#define CB_ELEMS (Q * K * D)
#define SCORE_OFFSET 1024.0f

// ---------------- device scratch (allocation-free rule) ----------------
__device__ float               g_res[NX_MAX];         // residual [N, D] fp32
__device__ __nv_bfloat16       g_rb[NX_MAX];          // residual bf16
__device__ __nv_bfloat16       g_cbb[CB_ELEMS];       // codebook bf16
__device__ float               g_c2[Q * K];           // exact ||c||^2
__device__ float               g_loss[Q];

// ---------------- helpers ----------------
__device__ __forceinline__ uint32_t smem_u32(const void* p) {
    uint32_t a;
    asm("{ .reg .u64 t; cvta.to.shared.u64 t, %1; cvt.u32.u64 %0, t; }"
        : "=r"(a) : "l"(p));
    return a;
}
__device__ __forceinline__ unsigned long long pack_key(float s, int code) {
    unsigned u = __float_as_uint(s);
    u = (u & 0x80000000u) ? ~u : (u | 0x80000000u);   // orderable fp32
    return ((unsigned long long)u << 32) | (unsigned)code;
}
__device__ __forceinline__ void cp16(uint32_t dst, const void* src) {
    asm volatile("cp.async.cg.shared.global [%0], [%1], 16;"
                 :: "r"(dst), "l"(src));
}
__device__ __forceinline__ void mbar_init(uint32_t m, uint32_t cnt) {
    asm volatile("mbarrier.init.shared.b64 [%0], %1;" :: "r"(m), "r"(cnt) : "memory");
}
__device__ __forceinline__ void mbar_arrive(uint32_t m) {
    asm volatile("mbarrier.arrive.shared.b64 _, [%0];" :: "r"(m) : "memory");
}
// NOINC: barrier count must equal the number of cp-arrive callers.
__device__ __forceinline__ void cp_arrive(uint32_t m) {
    asm volatile("cp.async.mbarrier.arrive.noinc.shared.b64 [%0];"
                 :: "r"(m) : "memory");
}
__device__ __forceinline__ void wait_parity(uint32_t m, uint32_t ph) {
    asm volatile(
        "{\n\t.reg .pred P;\n\t"
        "W%=:\n\t"
        "mbarrier.try_wait.parity.acquire.cta.shared::cta.b64 P, [%0], %1, 0x989680;\n\t"
        "@P bra D%=;\n\t"
        "bra W%=;\n\t"
        "D%=:\n\t}"
        :: "r"(m), "r"(ph) : "memory");
}
__device__ __forceinline__ void ldsm_x4(uint32_t& r0, uint32_t& r1,
                                        uint32_t& r2, uint32_t& r3, uint32_t a) {
    asm volatile("ldmatrix.sync.aligned.m8n8.x4.shared.b16 {%0,%1,%2,%3}, [%4];"
                 : "=r"(r0), "=r"(r1), "=r"(r2), "=r"(r3) : "r"(a));
}
__device__ __forceinline__ void mma16816(float* d, const uint32_t* a,
                                         const uint32_t* b) {
    asm volatile(
        "mma.sync.aligned.m16n8k16.row.col.f32.bf16.bf16.f32 "
        "{%0,%1,%2,%3},{%4,%5,%6,%7},{%8,%9},{%0,%1,%2,%3};"
        : "+f"(d[0]), "+f"(d[1]), "+f"(d[2]), "+f"(d[3])
        : "r"(a[0]), "r"(a[1]), "r"(a[2]), "r"(a[3]), "r"(b[0]), "r"(b[1]));
}
__device__ __forceinline__ ushort4 to_bf4(float4 v) {
    return ushort4{__bfloat16_as_ushort(__float2bfloat16_rn(v.x)),
                   __bfloat16_as_ushort(__float2bfloat16_rn(v.y)),
                   __bfloat16_as_ushort(__float2bfloat16_rn(v.z)),
                   __bfloat16_as_ushort(__float2bfloat16_rn(v.w))};
}
// float-key top-2 insert with id tracking; FMNMX/FSETP on fma pipe, SEL on alu
__device__ __forceinline__ void ins2f(float k, unsigned id,
                                      float& t0, unsigned& i0,
                                      float& t1, unsigned& i1) {
    bool p0 = k < t0;
    bool p1 = k < t1;
    float    nt1 = p1 ? k  : t1;
    unsigned ni1 = p1 ? id : i1;
    t1 = p0 ? t0 : nt1;
    i1 = p0 ? i0 : ni1;
    t0 = fminf(t0, k);
    i0 = p0 ? id : i0;
}

// ---------------------------------------------------------------------------
// residual = x (fp32 + bf16 mirror)
__global__ void copy_res_kernel(const float* __restrict__ x, int nx4) {
    int i = blockIdx.x * blockDim.x + threadIdx.x;
    if (i < nx4) {
        float4 v = reinterpret_cast<const float4*>(x)[i];
        reinterpret_cast<float4*>(g_res)[i] = v;
        reinterpret_cast<ushort4*>(g_rb)[i] = to_bf4(v);
    }
}

// exact ||c||^2 and zero losses
__global__ void c2_kernel(const float* __restrict__ cb) {
    if (blockIdx.x == 0 && threadIdx.x < Q) g_loss[threadIdx.x] = 0.f;
    int row  = blockIdx.x * 8 + (threadIdx.x >> 5);
    int lane = threadIdx.x & 31;
    const float* p = cb + (size_t)row * D;
    float s = 0.f;
#pragma unroll
    for (int t = 0; t < 2; t++) {
        float4 v = *reinterpret_cast<const float4*>(p + lane * 4 + t * 128);
        s += v.x * v.x + v.y * v.y + v.z * v.z + v.w * v.w;
    }
#pragma unroll
    for (int o = 16; o; o >>= 1) s += __shfl_down_sync(0xFFFFFFFFu, s, o);
    if (!lane) g_c2[row] = s;
}

__global__ void split_cb_kernel(const float* __restrict__ cb, int n4) {
    int i = blockIdx.x * blockDim.x + threadIdx.x;
    if (i < n4)
        reinterpret_cast<ushort4*>(g_cbb)[i] =
            to_bf4(reinterpret_cast<const float4*>(cb)[i]);
}

// ---------------------------------------------------------------------------
// Fused coarse + rescore + update kernel (see R9 notes).
#define A_OFF    16384
#define B_OFF    (16384 + 65536)
#define BUF_SZ   65536
#define MB_OFF   (B_OFF + 2 * BUF_SZ)
#define CAND_OFF (MB_OFF + 64)
#define LOSS_OFF (CAND_OFF + 128 * 8 * 4)
#define SMEM_SZ  (LOSS_OFF + 128 * 4)
#define CTHREADS 512

__global__ __launch_bounds__(CTHREADS, 1)
void coarse_kernel(const float* __restrict__ cbF, float* __restrict__ out,
                   int layer, int n_tok, int idx_base) {
    extern __shared__ char smem[];
    const int tid  = threadIdx.x;
    const int lane = tid & 31, wid = tid >> 5;
    const int warpM = wid >> 2, warpN = wid & 3;
    const int tokbase = blockIdx.x * 128;

    const uint32_t sb   = smem_u32(smem);
    const uint32_t a_sm = sb + A_OFF;
    const uint32_t b_sm = sb + B_OFF;
    const uint32_t mb_fill  = sb + MB_OFF;        // 2 x 8B
    const uint32_t mb_drain = sb + MB_OFF + 16;   // 2 x 8B
    float*    c2s     = reinterpret_cast<float*>(smem);
    unsigned* cand_sm = reinterpret_cast<unsigned*>(smem + CAND_OFF);
    float*    loss_sm = reinterpret_cast<float*>(smem + LOSS_OFF);

    const __nv_bfloat16* cbB = g_cbb + (size_t)layer * K * D;

    if (tid == 0) {
        mbar_init(mb_fill,      CTHREADS);
        mbar_init(mb_fill + 8,  CTHREADS);
        mbar_init(mb_drain,     16);
        mbar_init(mb_drain + 8, 16);
    }
    __syncthreads();

    // hoisted per-thread refill geometry: 8 slices of the 64KB chunk
    uint32_t roff[8];   // swizzled smem byte offset (loop-invariant)
    uint32_t soff[8];   // gmem element offset within a chunk (loop-invariant)
#pragma unroll
    for (int k = 0; k < 8; k++) {
        int i = tid + k * CTHREADS;
        int r = i >> 5, c = i & 31;
        roff[k] = (uint32_t)(r * 512 + ((c ^ (r & 7)) << 4));
        soff[k] = (uint32_t)(r * D + c * 8);
    }

    // prolog: issue chunks 0 and 1
#pragma unroll
    for (int pc = 0; pc < 2; pc++) {
        const __nv_bfloat16* src = cbB + (size_t)pc * 128 * D;
        uint32_t dstb = b_sm + pc * BUF_SZ;
#pragma unroll
        for (int k = 0; k < 8; k++) cp16(dstb + roff[k], src + soff[k]);
        cp_arrive(mb_fill + pc * 8);
    }

    // A tile (resident) + offset ||c||^2 slice
#pragma unroll
    for (int k = 0; k < 8; k++) {
        int i = tid + k * CTHREADS;
        int r = i >> 5, c = i & 31;
        uint4 v = *reinterpret_cast<const uint4*>(
            g_rb + (size_t)(tokbase + r) * D + c * 8);
        *reinterpret_cast<uint4*>(smem + A_OFF + roff[k]) = v;
    }
    for (int i = tid; i < 4096; i += CTHREADS)
        c2s[i] = g_c2[layer * K + i] + SCORE_OFFSET;
    __syncthreads();   // A + c2s visible to all warps

    // lane geometry for ldmatrix
    const int lrow  = ((lane >> 3) & 1) * 8 + (lane & 7);
    const int khalf = lane >> 4;
    uint32_t a_base[2]; int a_s7[2];
#pragma unroll
    for (int mi = 0; mi < 2; mi++) {
        int row = warpM * 32 + mi * 16 + lrow;
        a_base[mi] = a_sm + row * 512;
        a_s7[mi]   = row & 7;
    }
    uint32_t b_off[2]; int b_s7[2];
#pragma unroll
    for (int p = 0; p < 2; p++) {
        int row = warpN * 32 + p * 16 + lrow;
        b_off[p] = row * 512;
        b_s7[p]  = row & 7;
    }

    // running top-2 (float keys) + code ids, per token-row slot
    float    t0[4], t1[4];
    unsigned i0[4], i1[4];
#pragma unroll
    for (int s = 0; s < 4; s++) {
        t0[s] = __int_as_float(0x7f800000);
        t1[s] = __int_as_float(0x7f800000);
        i0[s] = 0u; i1[s] = 0u;
    }

    for (int ci = 0; ci < 32; ci++) {
        const int b  = ci & 1;
        const uint32_t ph = (unsigned)((ci >> 1) & 1);

        wait_parity(mb_fill + b * 8, ph);          // chunk ci data visible

        const uint32_t bbase = b_sm + b * BUF_SZ;
        float acc[2][4][4];
#pragma unroll
        for (int mi = 0; mi < 2; mi++)
#pragma unroll
            for (int nt = 0; nt < 4; nt++)
#pragma unroll
                for (int v = 0; v < 4; v++) acc[mi][nt][v] = 0.f;

#pragma unroll
        for (int ks = 0; ks < 16; ks++) {
            const int c = ks * 2 + khalf;
            uint32_t a[2][4];
#pragma unroll
            for (int mi = 0; mi < 2; mi++)
                ldsm_x4(a[mi][0], a[mi][1], a[mi][2], a[mi][3],
                        a_base[mi] + ((c ^ a_s7[mi]) << 4));
            uint32_t b2[4][2];
#pragma unroll
            for (int p = 0; p < 2; p++) {
                uint32_t r0, r1, r2, r3;
                ldsm_x4(r0, r1, r2, r3,
                        bbase + b_off[p] + ((c ^ b_s7[p]) << 4));
                b2[p * 2][0]     = r0; b2[p * 2][1]     = r2;
                b2[p * 2 + 1][0] = r1; b2[p * 2 + 1][1] = r3;
            }
#pragma unroll
            for (int mi = 0; mi < 2; mi++)
#pragma unroll
                for (int nt = 0; nt < 4; nt++)
                    mma16816(acc[mi][nt], a[mi], b2[nt]);
        }
        if (lane == 0) mbar_arrive(mb_drain + b * 8);   // my reads of buf b done

        // epilogue: float-key top-2 (overlaps other warps' MMA)
        const int innerbase = 2 * (lane & 3);
#pragma unroll
        for (int nt = 0; nt < 4; nt++) {
            const int col = ci * 128 + warpN * 32 + innerbase + nt * 8;
            float2 c2v = *reinterpret_cast<const float2*>(c2s + col);
#pragma unroll
            for (int mi = 0; mi < 2; mi++)
#pragma unroll
                for (int h = 0; h < 2; h++) {
                    float s0 = fmaf(-2.f, acc[mi][nt][h * 2 + 0], c2v.x);
                    float s1 = fmaf(-2.f, acc[mi][nt][h * 2 + 1], c2v.y);
                    const int s = mi * 2 + h;
                    ins2f(s0, (unsigned)col,       t0[s], i0[s], t1[s], i1[s]);
                    ins2f(s1, (unsigned)(col + 1), t0[s], i0[s], t1[s], i1[s]);
                }
        }

        if (ci < 30) {
            wait_parity(mb_drain + b * 8, ph);     // all warps done reading buf b
            const __nv_bfloat16* src = cbB + (size_t)(ci + 2) * 128 * D;
            uint32_t dstb = b_sm + b * BUF_SZ;
#pragma unroll
            for (int k = 0; k < 8; k++) cp16(dstb + roff[k], src + soff[k]);
            cp_arrive(mb_fill + b * 8);
        }
    }

    // quad merge (lanes sharing the same token rows); 2 candidates per warpN
    // group per token staged into smem
#pragma unroll
    for (int s = 0; s < 4; s++) {
        float    a0 = t0[s], a1 = t1[s];
        unsigned b0 = i0[s], b1 = i1[s];
#pragma unroll
        for (int o = 1; o <= 2; o <<= 1) {
            float    q0  = __shfl_xor_sync(0xFFFFFFFFu, a0, o);
            unsigned qi0 = __shfl_xor_sync(0xFFFFFFFFu, b0, o);
            float    q1  = __shfl_xor_sync(0xFFFFFFFFu, a1, o);
            unsigned qi1 = __shfl_xor_sync(0xFFFFFFFFu, b1, o);
            ins2f(q0, qi0, a0, b0, a1, b1);
            ins2f(q1, qi1, a0, b0, a1, b1);
        }
        if ((lane & 3) == 0) {
            int ltok = warpM * 32 + (s >> 1) * 16 + (s & 1) * 8 + (lane >> 2);
            cand_sm[ltok * 8 + warpN * 2]     = b0;
            cand_sm[ltok * 8 + warpN * 2 + 1] = b1;
        }
    }
    __syncthreads();

    // -------- fused tail: exact fp32 rescore + update, warp w -> 8 tokens ---
    // 4-way ILP: 4 candidate gathers in flight, interleaved butterfly.
    const float* cbL = cbF + (size_t)layer * K * D;
#pragma unroll 1
    for (int tt = 0; tt < 8; tt++) {
        const int ltok  = wid * 8 + tt;
        const int token = tokbase + ltok;
        unsigned mycode = cand_sm[ltok * 8 + (lane & 7)];

        float* rp = g_res + (size_t)token * D + lane * 8;
        float4 r0 = *reinterpret_cast<const float4*>(rp);
        float4 r1 = *reinterpret_cast<const float4*>(rp + 4);

        unsigned long long best = ~0ull;
#pragma unroll
        for (int half = 0; half < 2; half++) {
            int codes[4];
            float4 c0[4], c1[4];
#pragma unroll
            for (int j = 0; j < 4; j++) {
                codes[j] = (int)__shfl_sync(0xFFFFFFFFu, mycode, half * 4 + j);
                const float* c = cbL + (size_t)codes[j] * D + lane * 8;
                c0[j] = *reinterpret_cast<const float4*>(c);
                c1[j] = *reinterpret_cast<const float4*>(c + 4);
            }
            float dot[4];
#pragma unroll
            for (int j = 0; j < 4; j++) {
                float d0 = r0.x * c0[j].x;
                d0 = fmaf(r0.y, c0[j].y, d0); d0 = fmaf(r0.z, c0[j].z, d0);
                d0 = fmaf(r0.w, c0[j].w, d0); d0 = fmaf(r1.x, c1[j].x, d0);
                d0 = fmaf(r1.y, c1[j].y, d0); d0 = fmaf(r1.z, c1[j].z, d0);
                d0 = fmaf(r1.w, c1[j].w, d0);
                dot[j] = d0;
            }
#pragma unroll
            for (int o = 16; o; o >>= 1)
#pragma unroll
                for (int j = 0; j < 4; j++)
                    dot[j] += __shfl_xor_sync(0xFFFFFFFFu, dot[j], o);
#pragma unroll
            for (int j = 0; j < 4; j++) {
                float score = fmaf(-2.f, dot[j], g_c2[layer * K + codes[j]]);
                unsigned long long key = pack_key(score, codes[j]);
                best = key < best ? key : best;
            }
        }
        int idx = (int)(unsigned)(best & 0xFFFFFFFFull);

        // update: residual -= codeword; write fp32 (+ bf16 unless last layer)
        const float* q = cbL + (size_t)idx * D + lane * 8;
        float4 q0 = *reinterpret_cast<const float4*>(q);
        float4 q1 = *reinterpret_cast<const float4*>(q + 4);
        r0.x -= q0.x; r0.y -= q0.y; r0.z -= q0.z; r0.w -= q0.w;
        r1.x -= q1.x; r1.y -= q1.y; r1.z -= q1.z; r1.w -= q1.w;
        *reinterpret_cast<float4*>(rp)     = r0;
        *reinterpret_cast<float4*>(rp + 4) = r1;
        if (layer < Q - 1) {
            ushort4* bp = reinterpret_cast<ushort4*>(
                g_rb + (size_t)token * D + lane * 8);
            bp[0] = to_bf4(r0);
            bp[1] = to_bf4(r1);
        }
        float local = r0.x * r0.x + r0.y * r0.y + r0.z * r0.z + r0.w * r0.w
                    + r1.x * r1.x + r1.y * r1.y + r1.z * r1.z + r1.w * r1.w;
#pragma unroll
        for (int o = 16; o; o >>= 1)
            local += __shfl_down_sync(0xFFFFFFFFu, local, o);
        if (!lane) {
            out[idx_base + layer * n_tok + token] = (float)idx;
            loss_sm[ltok] = local;
        }
    }
    __syncthreads();
    if (wid == 0) {
        float s = loss_sm[lane] + loss_sm[lane + 32]
                + loss_sm[lane + 64] + loss_sm[lane + 96];
#pragma unroll
        for (int o = 16; o; o >>= 1) s += __shfl_down_sync(0xFFFFFFFFu, s, o);
        if (!lane) atomicAdd(&g_loss[layer], s);
    }
}

// ---------------------------------------------------------------------------
__global__ void finalize_kernel(const float* __restrict__ x,
                                float* __restrict__ out,
                                int nx4, int loss_off, float invND) {
    int i = blockIdx.x * blockDim.x + threadIdx.x;
    if (i < nx4) {
        float4 xv = reinterpret_cast<const float4*>(x)[i];
        float4 rv = reinterpret_cast<const float4*>(g_res)[i];
        float4 o;
        o.x = xv.x - rv.x; o.y = xv.y - rv.y;
        o.z = xv.z - rv.z; o.w = xv.w - rv.w;
        reinterpret_cast<float4*>(out)[i] = o;
    }
    if (blockIdx.x == 0 && threadIdx.x < Q)
        out[loss_off + threadIdx.x] = g_loss[threadIdx.x] * invND;
}

// ---------------------------------------------------------------------------
extern "C" void kernel_launch(void* const* d_in, const int* in_sizes, int n_in,
                              void* d_out, int out_size) {
    const float* x  = (const float*)d_in[0];   // [8, 4096, 256] fp32
    const float* cb = (const float*)d_in[1];   // [4, 4096, 256] fp32
    float* out = (float*)d_out;

    int nx    = in_sizes[0];      // 8388608
    int n_tok = nx / D;           // 32768
    int nx4   = nx / 4;

    cudaFuncSetAttribute(coarse_kernel,
                         cudaFuncAttributeMaxDynamicSharedMemorySize, SMEM_SZ);

    copy_res_kernel<<<(nx4 + 255) / 256, 256>>>(x, nx4);
    c2_kernel<<<(Q * K) / 8, 256>>>(cb);
    split_cb_kernel<<<(CB_ELEMS / 4 + 255) / 256, 256>>>(cb, CB_ELEMS / 4);

    for (int qi = 0; qi < Q; qi++)
        coarse_kernel<<<n_tok / 128, CTHREADS, SMEM_SZ>>>(cb, out, qi, n_tok, nx);

    finalize_kernel<<<(nx4 + 255) / 256, 256>>>(
        x, out, nx4, nx + Q * n_tok, 1.f / (float)nx);
}